// round 1
// baseline (speedup 1.0000x reference)
#include <cuda_runtime.h>
#include <cstdint>

// Problem constants
#define B_    2
#define S_    2048
#define H_    2048
#define NH    16
#define HD    128
#define MTOT  (B_ * S_)          // 4096
#define SCALE 11.313708498984761f // sqrt(128)

// Scratch (device globals: allocation-free rule)
__device__ float g_q[(size_t)B_ * NH * S_ * HD];   // [b][h][s][d]
__device__ float g_k[(size_t)B_ * NH * S_ * HD];
__device__ float g_v[(size_t)B_ * NH * S_ * HD];
__device__ float g_ctx[(size_t)B_ * S_ * H_];      // [b*s][h*hd]

// ---------------------------------------------------------------------------
// SGEMM core: C[m][n] = sum_k A[m][k] * W[n][k]
// A: [M x 2048] row-major, W: [2048 x 2048] row-major (both K-major).
// 128x128 tile, BK=16, 256 threads, 8x8 per-thread fragments.
// ---------------------------------------------------------------------------

// QKV projection with fused RoPE epilogue. gridDim.z selects Q/K/V.
__global__ __launch_bounds__(256, 2)
void qkv_kernel(const float* __restrict__ X,
                const float* __restrict__ Wq,
                const float* __restrict__ Wk,
                const float* __restrict__ Wv,
                const float* __restrict__ cs,
                const float* __restrict__ sn)
{
    __shared__ float As[16][132];
    __shared__ float Bs[16][132];

    const int z = blockIdx.z;
    const float* __restrict__ W = (z == 0) ? Wq : (z == 1) ? Wk : Wv;

    const int m0  = blockIdx.y * 128;
    const int n0  = blockIdx.x * 128;
    const int tid = threadIdx.x;
    const int tx  = tid & 15;
    const int ty  = tid >> 4;
    const int lr  = tid >> 2;          // 0..63
    const int lk  = (tid & 3) << 2;    // 0,4,8,12

    const float* Aptr = X + (size_t)(m0 + lr) * H_ + lk;
    const float* Bptr = W + (size_t)(n0 + lr) * H_ + lk;

    float acc[8][8];
    #pragma unroll
    for (int i = 0; i < 8; i++)
        #pragma unroll
        for (int j = 0; j < 8; j++) acc[i][j] = 0.f;

    for (int k0 = 0; k0 < H_; k0 += 16) {
        float4 a0 = *(const float4*)(Aptr + k0);
        float4 a1 = *(const float4*)(Aptr + k0 + (size_t)64 * H_);
        float4 b0 = *(const float4*)(Bptr + k0);
        float4 b1 = *(const float4*)(Bptr + k0 + (size_t)64 * H_);
        __syncthreads();
        As[lk + 0][lr] = a0.x; As[lk + 1][lr] = a0.y;
        As[lk + 2][lr] = a0.z; As[lk + 3][lr] = a0.w;
        As[lk + 0][64 + lr] = a1.x; As[lk + 1][64 + lr] = a1.y;
        As[lk + 2][64 + lr] = a1.z; As[lk + 3][64 + lr] = a1.w;
        Bs[lk + 0][lr] = b0.x; Bs[lk + 1][lr] = b0.y;
        Bs[lk + 2][lr] = b0.z; Bs[lk + 3][lr] = b0.w;
        Bs[lk + 0][64 + lr] = b1.x; Bs[lk + 1][64 + lr] = b1.y;
        Bs[lk + 2][64 + lr] = b1.z; Bs[lk + 3][64 + lr] = b1.w;
        __syncthreads();
        #pragma unroll
        for (int kk = 0; kk < 16; kk++) {
            float a[8], b[8];
            *(float4*)&a[0] = *(const float4*)&As[kk][ty * 4];
            *(float4*)&a[4] = *(const float4*)&As[kk][64 + ty * 4];
            *(float4*)&b[0] = *(const float4*)&Bs[kk][tx * 4];
            *(float4*)&b[4] = *(const float4*)&Bs[kk][64 + tx * 4];
            #pragma unroll
            for (int i = 0; i < 8; i++)
                #pragma unroll
                for (int j = 0; j < 8; j++)
                    acc[i][j] = fmaf(a[i], b[j], acc[i][j]);
        }
    }

    // Epilogue: write to [b][h][s][d] scratch. N-tile == one head.
    float* dst = (z == 0) ? g_q : (z == 1) ? g_k : g_v;
    const int h = blockIdx.x;

    #pragma unroll
    for (int i = 0; i < 8; i++) {
        int r = (i < 4) ? (ty * 4 + i) : (64 + ty * 4 + i - 4);
        int m = m0 + r;
        int b = m >> 11;         // / 2048
        int s = m & 2047;
        float* drow = dst + ((size_t)(b * NH + h) * S_ + s) * HD;
        if (z < 2) {
            // RoPE: pairs (c, c+64) are fragment cols (j, j+4)
            #pragma unroll
            for (int j = 0; j < 4; j++) {
                int dlo = tx * 4 + j;
                int dhi = dlo + 64;
                float cl = cs[s * HD + dlo], sl = sn[s * HD + dlo];
                float ch = cs[s * HD + dhi], sh = sn[s * HD + dhi];
                float vlo = acc[i][j], vhi = acc[i][j + 4];
                drow[dlo] = vlo * cl - vhi * sl;
                drow[dhi] = vhi * ch + vlo * sh;
            }
        } else {
            #pragma unroll
            for (int j = 0; j < 8; j++) {
                int c = (j < 4) ? (tx * 4 + j) : (64 + tx * 4 + j - 4);
                drow[c] = acc[i][j];
            }
        }
    }
}

// Output projection: out = g_ctx @ Wo^T
__global__ __launch_bounds__(256, 2)
void outproj_kernel(const float* __restrict__ Wo, float* __restrict__ out)
{
    __shared__ float As[16][132];
    __shared__ float Bs[16][132];

    const int m0  = blockIdx.y * 128;
    const int n0  = blockIdx.x * 128;
    const int tid = threadIdx.x;
    const int tx  = tid & 15;
    const int ty  = tid >> 4;
    const int lr  = tid >> 2;
    const int lk  = (tid & 3) << 2;

    const float* Aptr = g_ctx + (size_t)(m0 + lr) * H_ + lk;
    const float* Bptr = Wo    + (size_t)(n0 + lr) * H_ + lk;

    float acc[8][8];
    #pragma unroll
    for (int i = 0; i < 8; i++)
        #pragma unroll
        for (int j = 0; j < 8; j++) acc[i][j] = 0.f;

    for (int k0 = 0; k0 < H_; k0 += 16) {
        float4 a0 = *(const float4*)(Aptr + k0);
        float4 a1 = *(const float4*)(Aptr + k0 + (size_t)64 * H_);
        float4 b0 = *(const float4*)(Bptr + k0);
        float4 b1 = *(const float4*)(Bptr + k0 + (size_t)64 * H_);
        __syncthreads();
        As[lk + 0][lr] = a0.x; As[lk + 1][lr] = a0.y;
        As[lk + 2][lr] = a0.z; As[lk + 3][lr] = a0.w;
        As[lk + 0][64 + lr] = a1.x; As[lk + 1][64 + lr] = a1.y;
        As[lk + 2][64 + lr] = a1.z; As[lk + 3][64 + lr] = a1.w;
        Bs[lk + 0][lr] = b0.x; Bs[lk + 1][lr] = b0.y;
        Bs[lk + 2][lr] = b0.z; Bs[lk + 3][lr] = b0.w;
        Bs[lk + 0][64 + lr] = b1.x; Bs[lk + 1][64 + lr] = b1.y;
        Bs[lk + 2][64 + lr] = b1.z; Bs[lk + 3][64 + lr] = b1.w;
        __syncthreads();
        #pragma unroll
        for (int kk = 0; kk < 16; kk++) {
            float a[8], b[8];
            *(float4*)&a[0] = *(const float4*)&As[kk][ty * 4];
            *(float4*)&a[4] = *(const float4*)&As[kk][64 + ty * 4];
            *(float4*)&b[0] = *(const float4*)&Bs[kk][tx * 4];
            *(float4*)&b[4] = *(const float4*)&Bs[kk][64 + tx * 4];
            #pragma unroll
            for (int i = 0; i < 8; i++)
                #pragma unroll
                for (int j = 0; j < 8; j++)
                    acc[i][j] = fmaf(a[i], b[j], acc[i][j]);
        }
    }

    #pragma unroll
    for (int i = 0; i < 8; i++) {
        int r = (i < 4) ? (ty * 4 + i) : (64 + ty * 4 + i - 4);
        size_t m = m0 + r;
        #pragma unroll
        for (int j = 0; j < 8; j++) {
            int c = (j < 4) ? (tx * 4 + j) : (64 + tx * 4 + j - 4);
            out[m * H_ + n0 + c] = acc[i][j];
        }
    }
}

// ---------------------------------------------------------------------------
// Causal flash attention, fp32, BM=BN=128, D=128, 256 threads.
// sPt aliases sKt (K dead after S computed). smem = 196 KB.
// ---------------------------------------------------------------------------
#define QS 132  // padded stride for transposed Q/K/P tiles

__global__ __launch_bounds__(256, 1)
void attn_kernel()
{
    extern __shared__ float sm[];
    float* sQt = sm;                 // [128 d][132] transposed
    float* sKt = sm + 128 * QS;      // [128 d][132] transposed; aliased as sPt[c][132]
    float* sV  = sm + 2 * 128 * QS;  // [128 c][128 d] row-major

    const int tid = threadIdx.x;
    const int tx  = tid & 15;
    const int ty  = tid >> 4;
    const int qt  = (gridDim.x - 1) - blockIdx.x;  // largest q-tile first
    const int bh  = blockIdx.y;
    const int b   = bh >> 4;
    const int h   = bh & 15;
    const int q0  = qt * 128;
    const size_t base = (size_t)bh * S_ * HD;

    // Load Q tile transposed: sQt[d][r]
    #pragma unroll
    for (int it = 0; it < 16; it++) {
        int vec   = it * 256 + tid;
        int dpos  = vec & 7;
        int r     = (vec >> 3) & 127;
        int dbase = vec >> 10;
        int d     = dbase * 32 + dpos * 4;
        float4 v = *(const float4*)&g_q[base + (size_t)(q0 + r) * HD + d];
        sQt[(d + 0) * QS + r] = v.x;
        sQt[(d + 1) * QS + r] = v.y;
        sQt[(d + 2) * QS + r] = v.z;
        sQt[(d + 3) * QS + r] = v.w;
    }

    float o[8][8];
    float mrow[8], lrow[8];
    #pragma unroll
    for (int i = 0; i < 8; i++) {
        mrow[i] = -1e30f;
        lrow[i] = 0.f;
        #pragma unroll
        for (int j = 0; j < 8; j++) o[i][j] = 0.f;
    }

    for (int kt = 0; kt <= qt; kt++) {
        const int kb = kt * 128;
        __syncthreads();  // prev-iteration readers of sKt(/sPt) & sV done

        // Load K transposed, V row-major
        #pragma unroll
        for (int it = 0; it < 16; it++) {
            int vec   = it * 256 + tid;
            int dpos  = vec & 7;
            int r     = (vec >> 3) & 127;
            int dbase = vec >> 10;
            int d     = dbase * 32 + dpos * 4;
            float4 v = *(const float4*)&g_k[base + (size_t)(kb + r) * HD + d];
            sKt[(d + 0) * QS + r] = v.x;
            sKt[(d + 1) * QS + r] = v.y;
            sKt[(d + 2) * QS + r] = v.z;
            sKt[(d + 3) * QS + r] = v.w;
        }
        #pragma unroll
        for (int it = 0; it < 16; it++) {
            int vec = it * 256 + tid;
            int r   = vec >> 5;
            int dv  = (vec & 31) * 4;
            *(float4*)&sV[r * HD + dv] =
                *(const float4*)&g_v[base + (size_t)(kb + r) * HD + dv];
        }
        __syncthreads();

        // S = Q @ K^T (8x8 fragment, rows ty*8.., cols tx*8..)
        float sf[8][8];
        #pragma unroll
        for (int i = 0; i < 8; i++)
            #pragma unroll
            for (int j = 0; j < 8; j++) sf[i][j] = 0.f;

        #pragma unroll 8
        for (int d = 0; d < 128; d++) {
            float qv[8], kv[8];
            *(float4*)&qv[0] = *(const float4*)&sQt[d * QS + ty * 8];
            *(float4*)&qv[4] = *(const float4*)&sQt[d * QS + ty * 8 + 4];
            *(float4*)&kv[0] = *(const float4*)&sKt[d * QS + tx * 8];
            *(float4*)&kv[4] = *(const float4*)&sKt[d * QS + tx * 8 + 4];
            #pragma unroll
            for (int i = 0; i < 8; i++)
                #pragma unroll
                for (int j = 0; j < 8; j++)
                    sf[i][j] = fmaf(qv[i], kv[j], sf[i][j]);
        }

        const bool diag = (kt == qt);
        // Online softmax per row
        #pragma unroll
        for (int i = 0; i < 8; i++) {
            int rloc = ty * 8 + i;
            float mx = -1e30f;
            #pragma unroll
            for (int j = 0; j < 8; j++) {
                float v = sf[i][j] * SCALE;
                if (diag && (tx * 8 + j) > rloc) v = -1e30f;
                sf[i][j] = v;
                mx = fmaxf(mx, v);
            }
            #pragma unroll
            for (int off = 8; off > 0; off >>= 1)
                mx = fmaxf(mx, __shfl_xor_sync(0xffffffffu, mx, off));
            float mnew  = fmaxf(mrow[i], mx);
            float alpha = __expf(mrow[i] - mnew);
            mrow[i] = mnew;
            float ls = 0.f;
            #pragma unroll
            for (int j = 0; j < 8; j++) {
                float p = __expf(sf[i][j] - mnew);
                sf[i][j] = p;
                ls += p;
            }
            #pragma unroll
            for (int off = 8; off > 0; off >>= 1)
                ls += __shfl_xor_sync(0xffffffffu, ls, off);
            lrow[i] = lrow[i] * alpha + ls;
            #pragma unroll
            for (int j = 0; j < 8; j++) o[i][j] *= alpha;
        }

        __syncthreads();  // all threads done reading sKt
        // Write P transposed into sKt region: sPt[c][r]
        float* sPt = sKt;
        #pragma unroll
        for (int j = 0; j < 8; j++)
            #pragma unroll
            for (int i = 0; i < 8; i++)
                sPt[(tx * 8 + j) * QS + ty * 8 + i] = sf[i][j];
        __syncthreads();

        // O += P @ V  (rows ty*8.., d-cols tx*8..)
        #pragma unroll 4
        for (int c = 0; c < 128; c++) {
            float pv[8], vv[8];
            *(float4*)&pv[0] = *(const float4*)&sPt[c * QS + ty * 8];
            *(float4*)&pv[4] = *(const float4*)&sPt[c * QS + ty * 8 + 4];
            *(float4*)&vv[0] = *(const float4*)&sV[c * HD + tx * 8];
            *(float4*)&vv[4] = *(const float4*)&sV[c * HD + tx * 8 + 4];
            #pragma unroll
            for (int i = 0; i < 8; i++)
                #pragma unroll
                for (int j = 0; j < 8; j++)
                    o[i][j] = fmaf(pv[i], vv[j], o[i][j]);
        }
    }

    // Normalize and write ctx[b*s][h*hd+d]
    #pragma unroll
    for (int i = 0; i < 8; i++) {
        float inv = 1.0f / lrow[i];
        int s = q0 + ty * 8 + i;
        size_t off = ((size_t)(b * S_) + s) * H_ + h * HD + tx * 8;
        float4 w0 = make_float4(o[i][0] * inv, o[i][1] * inv,
                                o[i][2] * inv, o[i][3] * inv);
        float4 w1 = make_float4(o[i][4] * inv, o[i][5] * inv,
                                o[i][6] * inv, o[i][7] * inv);
        *(float4*)&g_ctx[off]     = w0;
        *(float4*)&g_ctx[off + 4] = w1;
    }
}

// ---------------------------------------------------------------------------
extern "C" void kernel_launch(void* const* d_in, const int* in_sizes, int n_in,
                              void* d_out, int out_size)
{
    (void)in_sizes; (void)n_in; (void)out_size;
    const float* x  = (const float*)d_in[0];
    const float* Wq = (const float*)d_in[1];
    const float* Wk = (const float*)d_in[2];
    const float* Wv = (const float*)d_in[3];
    const float* Wo = (const float*)d_in[4];
    const float* cs = (const float*)d_in[5];
    const float* sn = (const float*)d_in[6];
    float* out = (float*)d_out;

    // 1. Q/K/V projections + fused RoPE
    dim3 gq(H_ / 128, MTOT / 128, 3);
    qkv_kernel<<<gq, 256>>>(x, Wq, Wk, Wv, cs, sn);

    // 2. Causal flash attention
    size_t smem = (size_t)(2 * 128 * QS + 128 * HD) * sizeof(float);  // 200704 B
    cudaFuncSetAttribute(attn_kernel,
                         cudaFuncAttributeMaxDynamicSharedMemorySize, (int)smem);
    attn_kernel<<<dim3(S_ / 128, B_ * NH), 256, smem>>>();

    // 3. Output projection
    dim3 go(H_ / 128, MTOT / 128);
    outproj_kernel<<<go, 256>>>(Wo, out);
}

// round 3
// speedup vs baseline: 1.4903x; 1.4903x over previous
#include <cuda_runtime.h>
#include <cuda_bf16.h>
#include <cstdint>

#define B_    2
#define S_    2048
#define H_    2048
#define NH    16
#define HD    128
#define MTOT  (B_ * S_)           // 4096
#define SCALE 11.313708498984761f // sqrt(128)

// GEMM tiling
#define BK      32
#define NCH     (H_ / BK)          // 64 K-chunks
#define TSTRIDE 40                 // padded bf16 row stride in smem
#define TILE_B  (128 * TSTRIDE * 2)  // 10240 B per tile
#define BUF_B   (4 * TILE_B)         // Ah,Al,Wh,Wl
#define GEMM_SMEM (2 * BUF_B)        // 81920 B

// ---------------------------------------------------------------------------
// Device scratch
// ---------------------------------------------------------------------------
__device__ __nv_bfloat16 g_xh[(size_t)MTOT * H_];
__device__ __nv_bfloat16 g_xl[(size_t)MTOT * H_];
__device__ __nv_bfloat16 g_wh[4ull * H_ * H_];
__device__ __nv_bfloat16 g_wl[4ull * H_ * H_];
__device__ __nv_bfloat16 g_ch[(size_t)MTOT * H_];
__device__ __nv_bfloat16 g_cl[(size_t)MTOT * H_];
__device__ float g_q[(size_t)MTOT * H_];   // [b][h][s][d]
__device__ float g_k[(size_t)MTOT * H_];
__device__ float g_v[(size_t)MTOT * H_];

// ---------------------------------------------------------------------------
// PTX helpers (sm_80-level: ldmatrix / mma.sync / cp.async)
// ---------------------------------------------------------------------------
__device__ __forceinline__ uint32_t smem_u32(const void* p) {
    uint32_t a;
    asm("{ .reg .u64 t; cvta.to.shared.u64 t, %1; cvt.u32.u64 %0, t; }"
        : "=r"(a) : "l"(p));
    return a;
}

#define LDSM4(r, a) \
    asm volatile("ldmatrix.sync.aligned.m8n8.x4.shared.b16 {%0,%1,%2,%3}, [%4];" \
        : "=r"((r)[0]), "=r"((r)[1]), "=r"((r)[2]), "=r"((r)[3]) : "r"(a))

#define MMA(d, a, b0v, b1v) \
    asm volatile("mma.sync.aligned.m16n8k16.row.col.f32.bf16.bf16.f32 " \
        "{%0,%1,%2,%3},{%4,%5,%6,%7},{%8,%9},{%0,%1,%2,%3};" \
        : "+f"((d)[0]), "+f"((d)[1]), "+f"((d)[2]), "+f"((d)[3]) \
        : "r"((a)[0]), "r"((a)[1]), "r"((a)[2]), "r"((a)[3]), \
          "r"(b0v), "r"(b1v))

#define CPA16(dst, src) \
    asm volatile("cp.async.cg.shared.global [%0], [%1], 16;" \
        :: "r"(dst), "l"(src) : "memory")
#define CPA_COMMIT() asm volatile("cp.async.commit_group;" ::: "memory")
#define CPA_WAIT1()  asm volatile("cp.async.wait_group 1;" ::: "memory")
#define CPA_WAIT0()  asm volatile("cp.async.wait_group 0;" ::: "memory")

// ---------------------------------------------------------------------------
// Split-bf16 GEMM mainloop on mma.sync:
//   acc[128m x 128n] (fp32) += Ah*Wh^T + Ah*Wl^T + Al*Wh^T over K=2048.
// A, W are K-major bf16 (row stride H_). 256 threads, 8 warps (4m x 2n),
// warp tile 32x64, cp.async double-buffered smem.
// ---------------------------------------------------------------------------
__device__ __forceinline__ void prefetch_chunk(
    uint32_t sdst, const char* s0, const char* s1,
    const char* s2, const char* s3, int kc)
{
    const char* srcs[4] = { s0, s1, s2, s3 };
    const int tid = threadIdx.x;
    #pragma unroll
    for (int it = 0; it < 8; it++) {
        int idx  = it * 256 + tid;
        int tile = idx >> 9;
        int r    = (idx >> 2) & 127;
        int cv   = idx & 3;
        const char* src = srcs[tile] + (size_t)r * (H_ * 2) + kc * (BK * 2) + cv * 16;
        uint32_t dst = sdst + tile * TILE_B + (uint32_t)(r * TSTRIDE + cv * 8) * 2;
        CPA16(dst, src);
    }
    CPA_COMMIT();
}

__device__ __forceinline__ void gemm_main(
    const __nv_bfloat16* __restrict__ Ah, const __nv_bfloat16* __restrict__ Al,
    const __nv_bfloat16* __restrict__ Wh, const __nv_bfloat16* __restrict__ Wl,
    int m0, int n0, float acc[2][8][4])
{
    extern __shared__ char smx[];
    const uint32_t sbase = smem_u32(smx);
    const char* a0 = (const char*)(Ah + (size_t)m0 * H_);
    const char* a1 = (const char*)(Al + (size_t)m0 * H_);
    const char* b0 = (const char*)(Wh + (size_t)n0 * H_);
    const char* b1 = (const char*)(Wl + (size_t)n0 * H_);
    const int lane = threadIdx.x & 31;
    const int warp = threadIdx.x >> 5;
    const int wm = warp & 3;        // 4 warps along M (32 rows each)
    const int wn = warp >> 2;       // 2 warps along N (64 cols each)
    const int lrow = lane & 15;
    const int lk8  = (lane >> 4) * 8;

    prefetch_chunk(sbase, a0, a1, b0, b1, 0);

    for (int c = 0; c < NCH; c++) {
        const uint32_t sbuf = sbase + (uint32_t)(c & 1) * BUF_B;
        if (c + 1 < NCH) {
            prefetch_chunk(sbase + (uint32_t)((c + 1) & 1) * BUF_B,
                           a0, a1, b0, b1, c + 1);
            CPA_WAIT1();
        } else {
            CPA_WAIT0();
        }
        __syncthreads();

        #pragma unroll
        for (int ks = 0; ks < 2; ks++) {
            const int koff = ks * 16 + lk8;
            uint32_t ah[2][4], al[2][4];
            #pragma unroll
            for (int g = 0; g < 2; g++) {
                uint32_t addr = sbuf +
                    (uint32_t)((wm * 32 + g * 16 + lrow) * TSTRIDE + koff) * 2;
                LDSM4(ah[g], addr);
                LDSM4(al[g], addr + TILE_B);
            }
            uint32_t bh[4][4], bl[4][4];
            #pragma unroll
            for (int nb = 0; nb < 4; nb++) {
                uint32_t addr = sbuf + 2 * TILE_B +
                    (uint32_t)((wn * 64 + nb * 16 + lrow) * TSTRIDE + koff) * 2;
                LDSM4(bh[nb], addr);
                LDSM4(bl[nb], addr + TILE_B);
            }
            #pragma unroll
            for (int g = 0; g < 2; g++) {
                #pragma unroll
                for (int nb = 0; nb < 4; nb++) {
                    // lo n8 (cols nb*16+0..7): b = {R0, R2}; hi: {R1, R3}
                    MMA(acc[g][2 * nb],     ah[g], bh[nb][0], bh[nb][2]);
                    MMA(acc[g][2 * nb],     ah[g], bl[nb][0], bl[nb][2]);
                    MMA(acc[g][2 * nb],     al[g], bh[nb][0], bh[nb][2]);
                    MMA(acc[g][2 * nb + 1], ah[g], bh[nb][1], bh[nb][3]);
                    MMA(acc[g][2 * nb + 1], ah[g], bl[nb][1], bl[nb][3]);
                    MMA(acc[g][2 * nb + 1], al[g], bh[nb][1], bh[nb][3]);
                }
            }
        }
        __syncthreads();
    }
}

// Store fp32 accumulators into smem tile [128][132] (for epilogues that need
// cross-warp column access, e.g. RoPE pairing d with d+64).
__device__ __forceinline__ void acc_to_smem(float acc[2][8][4], float* smf)
{
    const int lane = threadIdx.x & 31;
    const int warp = threadIdx.x >> 5;
    const int wm = warp & 3, wn = warp >> 2;
    #pragma unroll
    for (int g = 0; g < 2; g++) {
        #pragma unroll
        for (int j = 0; j < 8; j++) {
            int row = wm * 32 + g * 16 + (lane >> 2);
            int col = wn * 64 + (j >> 1) * 16 + (j & 1) * 8 + 2 * (lane & 3);
            smf[row * 132 + col]       = acc[g][j][0];
            smf[row * 132 + col + 1]   = acc[g][j][1];
            smf[(row + 8) * 132 + col]     = acc[g][j][2];
            smf[(row + 8) * 132 + col + 1] = acc[g][j][3];
        }
    }
}

// ---------------------------------------------------------------------------
// QKV projection (blockIdx.z = 0/1/2 -> Q/K/V), RoPE fused for Q,K.
// ---------------------------------------------------------------------------
__global__ __launch_bounds__(256)
void qkv_mma_kernel(const float* __restrict__ cs, const float* __restrict__ sn)
{
    const int z    = blockIdx.z;
    const int head = blockIdx.x;
    const int m0   = blockIdx.y * 128;
    const int n0   = head * 128;

    float acc[2][8][4];
    #pragma unroll
    for (int g = 0; g < 2; g++)
        #pragma unroll
        for (int j = 0; j < 8; j++)
            #pragma unroll
            for (int e = 0; e < 4; e++) acc[g][j][e] = 0.f;

    gemm_main(g_xh, g_xl,
              g_wh + (size_t)z * H_ * H_,
              g_wl + (size_t)z * H_ * H_, m0, n0, acc);

    extern __shared__ char smx[];
    float* smf = (float*)smx;   // reuse tile buffers: 128*132*4 = 67584 <= 81920
    acc_to_smem(acc, smf);
    __syncthreads();

    const int t  = threadIdx.x;
    const int r  = t >> 1;
    const int dh = (t & 1) * 32;
    const int m  = m0 + r;
    const int s  = m & (S_ - 1);
    const int b  = m >> 11;
    float* dst   = (z == 0) ? g_q : (z == 1) ? g_k : g_v;
    float* drow  = dst + ((size_t)(b * NH + head) * S_ + s) * HD;

    if (z < 2) {
        const float* crow = cs + (size_t)s * HD;
        const float* srow = sn + (size_t)s * HD;
        #pragma unroll
        for (int j = 0; j < 32; j += 4) {
            float4 lo = *(const float4*)&smf[r * 132 + dh + j];
            float4 hi = *(const float4*)&smf[r * 132 + dh + j + 64];
            float4 c0 = *(const float4*)&crow[dh + j];
            float4 s0 = *(const float4*)&srow[dh + j];
            float4 c1 = *(const float4*)&crow[dh + j + 64];
            float4 s1 = *(const float4*)&srow[dh + j + 64];
            float4 olo, ohi;
            olo.x = lo.x * c0.x - hi.x * s0.x;  ohi.x = hi.x * c1.x + lo.x * s1.x;
            olo.y = lo.y * c0.y - hi.y * s0.y;  ohi.y = hi.y * c1.y + lo.y * s1.y;
            olo.z = lo.z * c0.z - hi.z * s0.z;  ohi.z = hi.z * c1.z + lo.z * s1.z;
            olo.w = lo.w * c0.w - hi.w * s0.w;  ohi.w = hi.w * c1.w + lo.w * s1.w;
            *(float4*)&drow[dh + j]      = olo;
            *(float4*)&drow[dh + j + 64] = ohi;
        }
    } else {
        #pragma unroll
        for (int j = 0; j < 32; j += 4) {
            *(float4*)&drow[dh + j]      = *(const float4*)&smf[r * 132 + dh + j];
            *(float4*)&drow[dh + j + 64] = *(const float4*)&smf[r * 132 + dh + j + 64];
        }
    }
}

// ---------------------------------------------------------------------------
// Output projection: out = ctx @ Wo^T, direct fragment stores.
// ---------------------------------------------------------------------------
__global__ __launch_bounds__(256)
void outproj_mma_kernel(float* __restrict__ out)
{
    const int m0 = blockIdx.y * 128;
    const int n0 = blockIdx.x * 128;

    float acc[2][8][4];
    #pragma unroll
    for (int g = 0; g < 2; g++)
        #pragma unroll
        for (int j = 0; j < 8; j++)
            #pragma unroll
            for (int e = 0; e < 4; e++) acc[g][j][e] = 0.f;

    gemm_main(g_ch, g_cl,
              g_wh + 3ull * H_ * H_,
              g_wl + 3ull * H_ * H_, m0, n0, acc);

    const int lane = threadIdx.x & 31;
    const int warp = threadIdx.x >> 5;
    const int wm = warp & 3, wn = warp >> 2;
    #pragma unroll
    for (int g = 0; g < 2; g++) {
        #pragma unroll
        for (int j = 0; j < 8; j++) {
            size_t row = (size_t)m0 + wm * 32 + g * 16 + (lane >> 2);
            int col = n0 + wn * 64 + (j >> 1) * 16 + (j & 1) * 8 + 2 * (lane & 3);
            *(float2*)&out[row * H_ + col] =
                make_float2(acc[g][j][0], acc[g][j][1]);
            *(float2*)&out[(row + 8) * H_ + col] =
                make_float2(acc[g][j][2], acc[g][j][3]);
        }
    }
}

// ---------------------------------------------------------------------------
// fp32 -> bf16 hi/lo split
// ---------------------------------------------------------------------------
__global__ void split_kernel(const float* __restrict__ src,
                             __nv_bfloat16* __restrict__ hi,
                             __nv_bfloat16* __restrict__ lo, int n4)
{
    int i = blockIdx.x * blockDim.x + threadIdx.x;
    if (i >= n4) return;
    float4 v = ((const float4*)src)[i];
    __nv_bfloat16 h0 = __float2bfloat16(v.x), h1 = __float2bfloat16(v.y);
    __nv_bfloat16 h2 = __float2bfloat16(v.z), h3 = __float2bfloat16(v.w);
    __nv_bfloat16 l0 = __float2bfloat16(v.x - __bfloat162float(h0));
    __nv_bfloat16 l1 = __float2bfloat16(v.y - __bfloat162float(h1));
    __nv_bfloat16 l2 = __float2bfloat16(v.z - __bfloat162float(h2));
    __nv_bfloat16 l3 = __float2bfloat16(v.w - __bfloat162float(h3));
    ((__nv_bfloat162*)hi)[2*i]   = __nv_bfloat162(h0, h1);
    ((__nv_bfloat162*)hi)[2*i+1] = __nv_bfloat162(h2, h3);
    ((__nv_bfloat162*)lo)[2*i]   = __nv_bfloat162(l0, l1);
    ((__nv_bfloat162*)lo)[2*i+1] = __nv_bfloat162(l2, l3);
}

// ---------------------------------------------------------------------------
// Causal flash attention, fp32 (unchanged core from R1). Epilogue writes ctx
// split to bf16 hi/lo for the output projection.
// ---------------------------------------------------------------------------
#define QS 132

__global__ __launch_bounds__(256, 1)
void attn_kernel()
{
    extern __shared__ float smf[];
    float* sQt = smf;
    float* sKt = smf + 128 * QS;
    float* sV  = smf + 2 * 128 * QS;

    const int tid = threadIdx.x;
    const int tx  = tid & 15;
    const int ty  = tid >> 4;
    const int qt  = (gridDim.x - 1) - blockIdx.x;
    const int bh  = blockIdx.y;
    const int b   = bh >> 4;
    const int h   = bh & 15;
    const int q0  = qt * 128;
    const size_t base = (size_t)bh * S_ * HD;

    #pragma unroll
    for (int it = 0; it < 16; it++) {
        int vec   = it * 256 + tid;
        int dpos  = vec & 7;
        int r     = (vec >> 3) & 127;
        int dbase = vec >> 10;
        int d     = dbase * 32 + dpos * 4;
        float4 v = *(const float4*)&g_q[base + (size_t)(q0 + r) * HD + d];
        sQt[(d + 0) * QS + r] = v.x;
        sQt[(d + 1) * QS + r] = v.y;
        sQt[(d + 2) * QS + r] = v.z;
        sQt[(d + 3) * QS + r] = v.w;
    }

    float o[8][8];
    float mrow[8], lrow[8];
    #pragma unroll
    for (int i = 0; i < 8; i++) {
        mrow[i] = -1e30f; lrow[i] = 0.f;
        #pragma unroll
        for (int j = 0; j < 8; j++) o[i][j] = 0.f;
    }

    for (int kt = 0; kt <= qt; kt++) {
        const int kb = kt * 128;
        __syncthreads();

        #pragma unroll
        for (int it = 0; it < 16; it++) {
            int vec   = it * 256 + tid;
            int dpos  = vec & 7;
            int r     = (vec >> 3) & 127;
            int dbase = vec >> 10;
            int d     = dbase * 32 + dpos * 4;
            float4 v = *(const float4*)&g_k[base + (size_t)(kb + r) * HD + d];
            sKt[(d + 0) * QS + r] = v.x;
            sKt[(d + 1) * QS + r] = v.y;
            sKt[(d + 2) * QS + r] = v.z;
            sKt[(d + 3) * QS + r] = v.w;
        }
        #pragma unroll
        for (int it = 0; it < 16; it++) {
            int vec = it * 256 + tid;
            int r   = vec >> 5;
            int dv  = (vec & 31) * 4;
            *(float4*)&sV[r * HD + dv] =
                *(const float4*)&g_v[base + (size_t)(kb + r) * HD + dv];
        }
        __syncthreads();

        float sf[8][8];
        #pragma unroll
        for (int i = 0; i < 8; i++)
            #pragma unroll
            for (int j = 0; j < 8; j++) sf[i][j] = 0.f;

        #pragma unroll 8
        for (int d = 0; d < 128; d++) {
            float qv[8], kv[8];
            *(float4*)&qv[0] = *(const float4*)&sQt[d * QS + ty * 8];
            *(float4*)&qv[4] = *(const float4*)&sQt[d * QS + ty * 8 + 4];
            *(float4*)&kv[0] = *(const float4*)&sKt[d * QS + tx * 8];
            *(float4*)&kv[4] = *(const float4*)&sKt[d * QS + tx * 8 + 4];
            #pragma unroll
            for (int i = 0; i < 8; i++)
                #pragma unroll
                for (int j = 0; j < 8; j++)
                    sf[i][j] = fmaf(qv[i], kv[j], sf[i][j]);
        }

        const bool diag = (kt == qt);
        #pragma unroll
        for (int i = 0; i < 8; i++) {
            int rloc = ty * 8 + i;
            float mx = -1e30f;
            #pragma unroll
            for (int j = 0; j < 8; j++) {
                float v = sf[i][j] * SCALE;
                if (diag && (tx * 8 + j) > rloc) v = -1e30f;
                sf[i][j] = v;
                mx = fmaxf(mx, v);
            }
            #pragma unroll
            for (int off = 8; off > 0; off >>= 1)
                mx = fmaxf(mx, __shfl_xor_sync(0xffffffffu, mx, off));
            float mnew  = fmaxf(mrow[i], mx);
            float alpha = __expf(mrow[i] - mnew);
            mrow[i] = mnew;
            float ls = 0.f;
            #pragma unroll
            for (int j = 0; j < 8; j++) {
                float p = __expf(sf[i][j] - mnew);
                sf[i][j] = p;
                ls += p;
            }
            #pragma unroll
            for (int off = 8; off > 0; off >>= 1)
                ls += __shfl_xor_sync(0xffffffffu, ls, off);
            lrow[i] = lrow[i] * alpha + ls;
            #pragma unroll
            for (int j = 0; j < 8; j++) o[i][j] *= alpha;
        }

        __syncthreads();
        float* sPt = sKt;
        #pragma unroll
        for (int j = 0; j < 8; j++)
            #pragma unroll
            for (int i = 0; i < 8; i++)
                sPt[(tx * 8 + j) * QS + ty * 8 + i] = sf[i][j];
        __syncthreads();

        #pragma unroll 4
        for (int c = 0; c < 128; c++) {
            float pv[8], vv[8];
            *(float4*)&pv[0] = *(const float4*)&sPt[c * QS + ty * 8];
            *(float4*)&pv[4] = *(const float4*)&sPt[c * QS + ty * 8 + 4];
            *(float4*)&vv[0] = *(const float4*)&sV[c * HD + tx * 8];
            *(float4*)&vv[4] = *(const float4*)&sV[c * HD + tx * 8 + 4];
            #pragma unroll
            for (int i = 0; i < 8; i++)
                #pragma unroll
                for (int j = 0; j < 8; j++)
                    o[i][j] = fmaf(pv[i], vv[j], o[i][j]);
        }
    }

    #pragma unroll
    for (int i = 0; i < 8; i++) {
        float inv = 1.0f / lrow[i];
        int s = q0 + ty * 8 + i;
        size_t off = ((size_t)(b * S_) + s) * H_ + h * HD + tx * 8;
        #pragma unroll
        for (int j = 0; j < 8; j++) {
            float v = o[i][j] * inv;
            __nv_bfloat16 hh = __float2bfloat16(v);
            g_ch[off + j] = hh;
            g_cl[off + j] = __float2bfloat16(v - __bfloat162float(hh));
        }
    }
}

// ---------------------------------------------------------------------------
extern "C" void kernel_launch(void* const* d_in, const int* in_sizes, int n_in,
                              void* d_out, int out_size)
{
    (void)in_sizes; (void)n_in; (void)out_size;
    const float* x  = (const float*)d_in[0];
    const float* W[4] = { (const float*)d_in[1], (const float*)d_in[2],
                          (const float*)d_in[3], (const float*)d_in[4] };
    const float* cs = (const float*)d_in[5];
    const float* sn = (const float*)d_in[6];
    float* out = (float*)d_out;

    void *pxh, *pxl, *pwh, *pwl;
    cudaGetSymbolAddress(&pxh, g_xh);
    cudaGetSymbolAddress(&pxl, g_xl);
    cudaGetSymbolAddress(&pwh, g_wh);
    cudaGetSymbolAddress(&pwl, g_wl);

    // 0. Split inputs to bf16 hi/lo
    {
        int n4 = MTOT * H_ / 4;
        split_kernel<<<(n4 + 255) / 256, 256>>>(x, (__nv_bfloat16*)pxh,
                                                (__nv_bfloat16*)pxl, n4);
        int w4 = H_ * H_ / 4;
        for (int w = 0; w < 4; w++)
            split_kernel<<<(w4 + 255) / 256, 256>>>(
                W[w],
                (__nv_bfloat16*)pwh + (size_t)w * H_ * H_,
                (__nv_bfloat16*)pwl + (size_t)w * H_ * H_, w4);
    }

    // 1. Q/K/V projections (split-bf16 mma.sync, RoPE fused)
    cudaFuncSetAttribute(qkv_mma_kernel,
                         cudaFuncAttributeMaxDynamicSharedMemorySize, GEMM_SMEM);
    qkv_mma_kernel<<<dim3(H_ / 128, MTOT / 128, 3), 256, GEMM_SMEM>>>(cs, sn);

    // 2. Causal flash attention (fp32), writes ctx as bf16 hi/lo
    size_t asmem = (size_t)(2 * 128 * QS + 128 * HD) * sizeof(float);
    cudaFuncSetAttribute(attn_kernel,
                         cudaFuncAttributeMaxDynamicSharedMemorySize, (int)asmem);
    attn_kernel<<<dim3(S_ / 128, B_ * NH), 256, asmem>>>();

    // 3. Output projection (split-bf16 mma.sync)
    cudaFuncSetAttribute(outproj_mma_kernel,
                         cudaFuncAttributeMaxDynamicSharedMemorySize, GEMM_SMEM);
    outproj_mma_kernel<<<dim3(H_ / 128, MTOT / 128), 256, GEMM_SMEM>>>(out);
}

// round 5
// speedup vs baseline: 1.7897x; 1.2008x over previous
#include <cuda_runtime.h>
#include <cuda_bf16.h>
#include <cuda_fp16.h>
#include <cstdint>

#define B_    2
#define S_    2048
#define H_    2048
#define NH    16
#define HD    128
#define MTOT  (B_ * S_)           // 4096
#define SCALE 11.313708498984761f // sqrt(128)

// GEMM tiling (unchanged from R3)
#define BK      32
#define NCH     (H_ / BK)
#define TSTRIDE 40
#define TILE_B  (128 * TSTRIDE * 2)
#define BUF_B   (4 * TILE_B)
#define GEMM_SMEM (2 * BUF_B)

// Attention smem: 6 half tiles [128][136]
#define AST 136
#define ATILE (128 * AST)              // halves per tile
#define ATTN_SMEM (6 * ATILE * 2)      // 208896 B

// ---------------------------------------------------------------------------
// Device scratch
// ---------------------------------------------------------------------------
__device__ __nv_bfloat16 g_xh[(size_t)MTOT * H_];
__device__ __nv_bfloat16 g_xl[(size_t)MTOT * H_];
__device__ __nv_bfloat16 g_wh[4ull * H_ * H_];
__device__ __nv_bfloat16 g_wl[4ull * H_ * H_];
__device__ __nv_bfloat16 g_ch[(size_t)MTOT * H_];
__device__ __nv_bfloat16 g_cl[(size_t)MTOT * H_];
__device__ __half g_qh[(size_t)MTOT * H_];   // [b][h][s][d] fp16 hi (post-RoPE)
__device__ __half g_ql[(size_t)MTOT * H_];   // fp16 lo
__device__ __half g_kh[(size_t)MTOT * H_];
__device__ __half g_kl[(size_t)MTOT * H_];
__device__ __half g_vh[(size_t)MTOT * H_];
__device__ __half g_vl[(size_t)MTOT * H_];

// ---------------------------------------------------------------------------
// PTX helpers
// ---------------------------------------------------------------------------
__device__ __forceinline__ uint32_t smem_u32(const void* p) {
    uint32_t a;
    asm("{ .reg .u64 t; cvta.to.shared.u64 t, %1; cvt.u32.u64 %0, t; }"
        : "=r"(a) : "l"(p));
    return a;
}

#define LDSM4(r, a) \
    asm volatile("ldmatrix.sync.aligned.m8n8.x4.shared.b16 {%0,%1,%2,%3}, [%4];" \
        : "=r"((r)[0]), "=r"((r)[1]), "=r"((r)[2]), "=r"((r)[3]) : "r"(a))
#define LDSM4T(r, a) \
    asm volatile("ldmatrix.sync.aligned.m8n8.x4.trans.shared.b16 {%0,%1,%2,%3}, [%4];" \
        : "=r"((r)[0]), "=r"((r)[1]), "=r"((r)[2]), "=r"((r)[3]) : "r"(a))

#define MMAB(d, a, b0v, b1v) \
    asm volatile("mma.sync.aligned.m16n8k16.row.col.f32.bf16.bf16.f32 " \
        "{%0,%1,%2,%3},{%4,%5,%6,%7},{%8,%9},{%0,%1,%2,%3};" \
        : "+f"((d)[0]), "+f"((d)[1]), "+f"((d)[2]), "+f"((d)[3]) \
        : "r"((a)[0]), "r"((a)[1]), "r"((a)[2]), "r"((a)[3]), \
          "r"(b0v), "r"(b1v))
#define MMAH(d, a, b0v, b1v) \
    asm volatile("mma.sync.aligned.m16n8k16.row.col.f32.f16.f16.f32 " \
        "{%0,%1,%2,%3},{%4,%5,%6,%7},{%8,%9},{%0,%1,%2,%3};" \
        : "+f"((d)[0]), "+f"((d)[1]), "+f"((d)[2]), "+f"((d)[3]) \
        : "r"((a)[0]), "r"((a)[1]), "r"((a)[2]), "r"((a)[3]), \
          "r"(b0v), "r"(b1v))

#define CPA16(dst, src) \
    asm volatile("cp.async.cg.shared.global [%0], [%1], 16;" \
        :: "r"(dst), "l"(src) : "memory")
#define CPA_COMMIT() asm volatile("cp.async.commit_group;" ::: "memory")
#define CPA_WAIT1()  asm volatile("cp.async.wait_group 1;" ::: "memory")
#define CPA_WAIT0()  asm volatile("cp.async.wait_group 0;" ::: "memory")

// ---------------------------------------------------------------------------
// Split-bf16 GEMM (unchanged from R3)
// ---------------------------------------------------------------------------
__device__ __forceinline__ void prefetch_chunk(
    uint32_t sdst, const char* s0, const char* s1,
    const char* s2, const char* s3, int kc)
{
    const char* srcs[4] = { s0, s1, s2, s3 };
    const int tid = threadIdx.x;
    #pragma unroll
    for (int it = 0; it < 8; it++) {
        int idx  = it * 256 + tid;
        int tile = idx >> 9;
        int r    = (idx >> 2) & 127;
        int cv   = idx & 3;
        const char* src = srcs[tile] + (size_t)r * (H_ * 2) + kc * (BK * 2) + cv * 16;
        uint32_t dst = sdst + tile * TILE_B + (uint32_t)(r * TSTRIDE + cv * 8) * 2;
        CPA16(dst, src);
    }
    CPA_COMMIT();
}

__device__ __forceinline__ void gemm_main(
    const __nv_bfloat16* __restrict__ Ah, const __nv_bfloat16* __restrict__ Al,
    const __nv_bfloat16* __restrict__ Wh, const __nv_bfloat16* __restrict__ Wl,
    int m0, int n0, float acc[2][8][4])
{
    extern __shared__ char smx[];
    const uint32_t sbase = smem_u32(smx);
    const char* a0 = (const char*)(Ah + (size_t)m0 * H_);
    const char* a1 = (const char*)(Al + (size_t)m0 * H_);
    const char* b0 = (const char*)(Wh + (size_t)n0 * H_);
    const char* b1 = (const char*)(Wl + (size_t)n0 * H_);
    const int lane = threadIdx.x & 31;
    const int warp = threadIdx.x >> 5;
    const int wm = warp & 3;
    const int wn = warp >> 2;
    const int lrow = lane & 15;
    const int lk8  = (lane >> 4) * 8;

    prefetch_chunk(sbase, a0, a1, b0, b1, 0);

    for (int c = 0; c < NCH; c++) {
        const uint32_t sbuf = sbase + (uint32_t)(c & 1) * BUF_B;
        if (c + 1 < NCH) {
            prefetch_chunk(sbase + (uint32_t)((c + 1) & 1) * BUF_B,
                           a0, a1, b0, b1, c + 1);
            CPA_WAIT1();
        } else {
            CPA_WAIT0();
        }
        __syncthreads();

        #pragma unroll
        for (int ks = 0; ks < 2; ks++) {
            const int koff = ks * 16 + lk8;
            uint32_t ah[2][4], al[2][4];
            #pragma unroll
            for (int g = 0; g < 2; g++) {
                uint32_t addr = sbuf +
                    (uint32_t)((wm * 32 + g * 16 + lrow) * TSTRIDE + koff) * 2;
                LDSM4(ah[g], addr);
                LDSM4(al[g], addr + TILE_B);
            }
            uint32_t bh[4][4], bl[4][4];
            #pragma unroll
            for (int nb = 0; nb < 4; nb++) {
                uint32_t addr = sbuf + 2 * TILE_B +
                    (uint32_t)((wn * 64 + nb * 16 + lrow) * TSTRIDE + koff) * 2;
                LDSM4(bh[nb], addr);
                LDSM4(bl[nb], addr + TILE_B);
            }
            #pragma unroll
            for (int g = 0; g < 2; g++) {
                #pragma unroll
                for (int nb = 0; nb < 4; nb++) {
                    MMAB(acc[g][2 * nb],     ah[g], bh[nb][0], bh[nb][2]);
                    MMAB(acc[g][2 * nb],     ah[g], bl[nb][0], bl[nb][2]);
                    MMAB(acc[g][2 * nb],     al[g], bh[nb][0], bh[nb][2]);
                    MMAB(acc[g][2 * nb + 1], ah[g], bh[nb][1], bh[nb][3]);
                    MMAB(acc[g][2 * nb + 1], ah[g], bl[nb][1], bl[nb][3]);
                    MMAB(acc[g][2 * nb + 1], al[g], bh[nb][1], bh[nb][3]);
                }
            }
        }
        __syncthreads();
    }
}

__device__ __forceinline__ void acc_to_smem(float acc[2][8][4], float* smf)
{
    const int lane = threadIdx.x & 31;
    const int warp = threadIdx.x >> 5;
    const int wm = warp & 3, wn = warp >> 2;
    #pragma unroll
    for (int g = 0; g < 2; g++) {
        #pragma unroll
        for (int j = 0; j < 8; j++) {
            int row = wm * 32 + g * 16 + (lane >> 2);
            int col = wn * 64 + (j >> 1) * 16 + (j & 1) * 8 + 2 * (lane & 3);
            smf[row * 132 + col]           = acc[g][j][0];
            smf[row * 132 + col + 1]       = acc[g][j][1];
            smf[(row + 8) * 132 + col]     = acc[g][j][2];
            smf[(row + 8) * 132 + col + 1] = acc[g][j][3];
        }
    }
}

// ---------------------------------------------------------------------------
// QKV projection; RoPE fused; writes Q,K,V all as fp16 hi/lo.
// ---------------------------------------------------------------------------
__global__ __launch_bounds__(256)
void qkv_mma_kernel(const float* __restrict__ cs, const float* __restrict__ sn)
{
    const int z    = blockIdx.z;
    const int head = blockIdx.x;
    const int m0   = blockIdx.y * 128;
    const int n0   = head * 128;

    float acc[2][8][4];
    #pragma unroll
    for (int g = 0; g < 2; g++)
        #pragma unroll
        for (int j = 0; j < 8; j++)
            #pragma unroll
            for (int e = 0; e < 4; e++) acc[g][j][e] = 0.f;

    gemm_main(g_xh, g_xl,
              g_wh + (size_t)z * H_ * H_,
              g_wl + (size_t)z * H_ * H_, m0, n0, acc);

    extern __shared__ char smx[];
    float* smf = (float*)smx;
    acc_to_smem(acc, smf);
    __syncthreads();

    const int t  = threadIdx.x;
    const int r  = t >> 1;
    const int dh = (t & 1) * 32;
    const int m  = m0 + r;
    const int s  = m & (S_ - 1);
    const int b  = m >> 11;
    const size_t rowbase = ((size_t)(b * NH + head) * S_ + s) * HD;

    __half* dsth = (z == 0) ? g_qh : (z == 1) ? g_kh : g_vh;
    __half* dstl = (z == 0) ? g_ql : (z == 1) ? g_kl : g_vl;
    dsth += rowbase;
    dstl += rowbase;

    if (z < 2) {
        const float* crow = cs + (size_t)s * HD;
        const float* srow = sn + (size_t)s * HD;
        #pragma unroll
        for (int j = 0; j < 32; j++) {
            float lo = smf[r * 132 + dh + j];
            float hi = smf[r * 132 + dh + j + 64];
            float olo = lo * crow[dh + j]      - hi * srow[dh + j];
            float ohi = hi * crow[dh + j + 64] + lo * srow[dh + j + 64];
            __half a = __float2half_rn(olo);
            __half bq = __float2half_rn(ohi);
            dsth[dh + j]      = a;
            dsth[dh + j + 64] = bq;
            dstl[dh + j]      = __float2half_rn(olo - __half2float(a));
            dstl[dh + j + 64] = __float2half_rn(ohi - __half2float(bq));
        }
    } else {
        #pragma unroll
        for (int j = 0; j < 32; j++) {
            #pragma unroll
            for (int half_ = 0; half_ < 2; half_++) {
                int c = dh + j + half_ * 64;
                float v = smf[r * 132 + c];
                __half vh = __float2half_rn(v);
                dsth[c] = vh;
                dstl[c] = __float2half_rn(v - __half2float(vh));
            }
        }
    }
}

// ---------------------------------------------------------------------------
// Output projection (unchanged)
// ---------------------------------------------------------------------------
__global__ __launch_bounds__(256)
void outproj_mma_kernel(float* __restrict__ out)
{
    const int m0 = blockIdx.y * 128;
    const int n0 = blockIdx.x * 128;

    float acc[2][8][4];
    #pragma unroll
    for (int g = 0; g < 2; g++)
        #pragma unroll
        for (int j = 0; j < 8; j++)
            #pragma unroll
            for (int e = 0; e < 4; e++) acc[g][j][e] = 0.f;

    gemm_main(g_ch, g_cl,
              g_wh + 3ull * H_ * H_,
              g_wl + 3ull * H_ * H_, m0, n0, acc);

    const int lane = threadIdx.x & 31;
    const int warp = threadIdx.x >> 5;
    const int wm = warp & 3, wn = warp >> 2;
    #pragma unroll
    for (int g = 0; g < 2; g++) {
        #pragma unroll
        for (int j = 0; j < 8; j++) {
            size_t row = (size_t)m0 + wm * 32 + g * 16 + (lane >> 2);
            int col = n0 + wn * 64 + (j >> 1) * 16 + (j & 1) * 8 + 2 * (lane & 3);
            *(float2*)&out[row * H_ + col] =
                make_float2(acc[g][j][0], acc[g][j][1]);
            *(float2*)&out[(row + 8) * H_ + col] =
                make_float2(acc[g][j][2], acc[g][j][3]);
        }
    }
}

// ---------------------------------------------------------------------------
// fp32 -> bf16 hi/lo split
// ---------------------------------------------------------------------------
__global__ void split_kernel(const float* __restrict__ src,
                             __nv_bfloat16* __restrict__ hi,
                             __nv_bfloat16* __restrict__ lo, int n4)
{
    int i = blockIdx.x * blockDim.x + threadIdx.x;
    if (i >= n4) return;
    float4 v = ((const float4*)src)[i];
    __nv_bfloat16 h0 = __float2bfloat16(v.x), h1 = __float2bfloat16(v.y);
    __nv_bfloat16 h2 = __float2bfloat16(v.z), h3 = __float2bfloat16(v.w);
    __nv_bfloat16 l0 = __float2bfloat16(v.x - __bfloat162float(h0));
    __nv_bfloat16 l1 = __float2bfloat16(v.y - __bfloat162float(h1));
    __nv_bfloat16 l2 = __float2bfloat16(v.z - __bfloat162float(h2));
    __nv_bfloat16 l3 = __float2bfloat16(v.w - __bfloat162float(h3));
    ((__nv_bfloat162*)hi)[2*i]   = __nv_bfloat162(h0, h1);
    ((__nv_bfloat162*)hi)[2*i+1] = __nv_bfloat162(h2, h3);
    ((__nv_bfloat162*)lo)[2*i]   = __nv_bfloat162(l0, l1);
    ((__nv_bfloat162*)lo)[2*i+1] = __nv_bfloat162(l2, l3);
}

// ---------------------------------------------------------------------------
// Tensor-core causal flash attention (fp16 mma.sync, split-fp16 QK^T).
//   S = Qh·Kh + Qh·Kl + Ql·Kh;  O += P(fp16)·(Vh + Vl).
// 8 warps, each owns 16 Q rows. BM=BN=128.
// ---------------------------------------------------------------------------
__global__ __launch_bounds__(256, 1)
void attn_mma_kernel()
{
    extern __shared__ char smem[];
    __half* sQh = (__half*)smem;           // [128][AST]
    __half* sQl = sQh + ATILE;
    __half* sKh = sQl + ATILE;
    __half* sKl = sKh + ATILE;
    __half* sVh = sKl + ATILE;
    __half* sVl = sVh + ATILE;

    const int tid  = threadIdx.x;
    const int lane = tid & 31;
    const int warp = tid >> 5;
    const int lrow = lane & 7;
    const int lq   = lane >> 3;
    const int qt   = (gridDim.x - 1) - blockIdx.x;
    const int bh   = blockIdx.y;
    const int q0   = qt * 128;
    const size_t base = (size_t)bh * S_ * HD;

    const uint32_t sQh_u = smem_u32(sQh);
    const uint32_t sQl_u = smem_u32(sQl);
    const uint32_t sKh_u = smem_u32(sKh);
    const uint32_t sKl_u = smem_u32(sKl);
    const uint32_t sVh_u = smem_u32(sVh);
    const uint32_t sVl_u = smem_u32(sVl);

    // Load Q hi/lo tiles
    #pragma unroll
    for (int it = 0; it < 8; it++) {
        int idx = it * 256 + tid;
        int r   = idx >> 4;
        int c8  = (idx & 15) * 8;
        size_t g = base + (size_t)(q0 + r) * HD + c8;
        uint32_t so = (uint32_t)(r * AST + c8) * 2;
        CPA16(sQh_u + so, (const char*)&g_qh[g]);
        CPA16(sQl_u + so, (const char*)&g_ql[g]);
    }
    CPA_COMMIT();
    CPA_WAIT0();
    __syncthreads();

    // Q A-fragments (hi and lo) in registers
    uint32_t qfh[8][4], qfl[8][4];
    {
        int row = warp * 16 + ((lq & 1) ? 8 : 0) + lrow;
        #pragma unroll
        for (int ks = 0; ks < 8; ks++) {
            int col = ks * 16 + ((lq & 2) ? 8 : 0);
            uint32_t so = (uint32_t)(row * AST + col) * 2;
            LDSM4(qfh[ks], sQh_u + so);
            LDSM4(qfl[ks], sQl_u + so);
        }
    }

    float o[16][4];
    #pragma unroll
    for (int j = 0; j < 16; j++)
        #pragma unroll
        for (int e = 0; e < 4; e++) o[j][e] = 0.f;
    float mr[2] = { -1e30f, -1e30f };
    float lr_[2] = { 0.f, 0.f };

    const int krow_b = ((lq & 2) ? 8 : 0) + lrow;
    const int kcol_b = ((lq & 1) ? 8 : 0);
    const int vrow_b = ((lq & 1) ? 8 : 0) + lrow;
    const int vcol_b = ((lq & 2) ? 8 : 0);
    const int myrow  = lane >> 2;
    const int mycol  = 2 * (lane & 3);

    for (int kt = 0; kt <= qt; kt++) {
        const int kb = kt * 128;
        __syncthreads();

        #pragma unroll
        for (int it = 0; it < 8; it++) {
            int idx = it * 256 + tid;
            int r   = idx >> 4;
            int c8  = (idx & 15) * 8;
            size_t g = base + (size_t)(kb + r) * HD + c8;
            uint32_t so = (uint32_t)(r * AST + c8) * 2;
            CPA16(sKh_u + so, (const char*)&g_kh[g]);
            CPA16(sKl_u + so, (const char*)&g_kl[g]);
            CPA16(sVh_u + so, (const char*)&g_vh[g]);
            CPA16(sVl_u + so, (const char*)&g_vl[g]);
        }
        CPA_COMMIT();
        CPA_WAIT0();
        __syncthreads();

        // ---- S = Qh Kh^T + Qh Kl^T + Ql Kh^T ----
        float sf[16][4];
        #pragma unroll
        for (int j = 0; j < 16; j++)
            #pragma unroll
            for (int e = 0; e < 4; e++) sf[j][e] = 0.f;

        #pragma unroll
        for (int ks = 0; ks < 8; ks++) {
            #pragma unroll
            for (int jj = 0; jj < 8; jj++) {
                int row = jj * 16 + krow_b;
                int col = ks * 16 + kcol_b;
                uint32_t so = (uint32_t)(row * AST + col) * 2;
                uint32_t kfh[4], kfl[4];
                LDSM4(kfh, sKh_u + so);
                LDSM4(kfl, sKl_u + so);
                MMAH(sf[2 * jj],     qfh[ks], kfh[0], kfh[1]);
                MMAH(sf[2 * jj],     qfh[ks], kfl[0], kfl[1]);
                MMAH(sf[2 * jj],     qfl[ks], kfh[0], kfh[1]);
                MMAH(sf[2 * jj + 1], qfh[ks], kfh[2], kfh[3]);
                MMAH(sf[2 * jj + 1], qfh[ks], kfl[2], kfl[3]);
                MMAH(sf[2 * jj + 1], qfl[ks], kfh[2], kfh[3]);
            }
        }

        // ---- online softmax ----
        const bool diag = (kt == qt);
        const int grow0 = q0 + warp * 16 + myrow;
        #pragma unroll
        for (int rr = 0; rr < 2; rr++) {
            const int grow = grow0 + rr * 8;
            float mx = -1e30f;
            #pragma unroll
            for (int j = 0; j < 16; j++) {
                #pragma unroll
                for (int e = 0; e < 2; e++) {
                    float v = sf[j][rr * 2 + e] * SCALE;
                    if (diag && (kb + j * 8 + mycol + e) > grow) v = -1e30f;
                    sf[j][rr * 2 + e] = v;
                    mx = fmaxf(mx, v);
                }
            }
            mx = fmaxf(mx, __shfl_xor_sync(0xffffffffu, mx, 1));
            mx = fmaxf(mx, __shfl_xor_sync(0xffffffffu, mx, 2));
            float mnew  = fmaxf(mr[rr], mx);
            float alpha = __expf(mr[rr] - mnew);
            mr[rr] = mnew;
            float ls = 0.f;
            #pragma unroll
            for (int j = 0; j < 16; j++) {
                #pragma unroll
                for (int e = 0; e < 2; e++) {
                    float p = __expf(sf[j][rr * 2 + e] - mnew);
                    sf[j][rr * 2 + e] = p;
                    ls += p;
                }
            }
            ls += __shfl_xor_sync(0xffffffffu, ls, 1);
            ls += __shfl_xor_sync(0xffffffffu, ls, 2);
            lr_[rr] = lr_[rr] * alpha + ls;
            #pragma unroll
            for (int j = 0; j < 16; j++) {
                o[j][rr * 2]     *= alpha;
                o[j][rr * 2 + 1] *= alpha;
            }
        }

        // ---- pack P to fp16 A-frags ----
        uint32_t pf[8][4];
        #pragma unroll
        for (int j = 0; j < 8; j++) {
            __half2 h;
            h = __floats2half2_rn(sf[2*j][0],   sf[2*j][1]);   pf[j][0] = *(uint32_t*)&h;
            h = __floats2half2_rn(sf[2*j][2],   sf[2*j][3]);   pf[j][1] = *(uint32_t*)&h;
            h = __floats2half2_rn(sf[2*j+1][0], sf[2*j+1][1]); pf[j][2] = *(uint32_t*)&h;
            h = __floats2half2_rn(sf[2*j+1][2], sf[2*j+1][3]); pf[j][3] = *(uint32_t*)&h;
        }

        // ---- O += P (Vh + Vl) ----
        #pragma unroll
        for (int j = 0; j < 8; j++) {
            int row = j * 16 + vrow_b;
            #pragma unroll
            for (int dd = 0; dd < 8; dd++) {
                int col = dd * 16 + vcol_b;
                uint32_t so = (uint32_t)(row * AST + col) * 2;
                uint32_t vf[4];
                LDSM4T(vf, sVh_u + so);
                MMAH(o[2 * dd],     pf[j], vf[0], vf[1]);
                MMAH(o[2 * dd + 1], pf[j], vf[2], vf[3]);
                LDSM4T(vf, sVl_u + so);
                MMAH(o[2 * dd],     pf[j], vf[0], vf[1]);
                MMAH(o[2 * dd + 1], pf[j], vf[2], vf[3]);
            }
        }
    }

    // ---- epilogue: normalize, split to bf16 hi/lo ----
    const int b = bh >> 4;
    const int h = bh & 15;
    float inv0 = 1.0f / lr_[0];
    float inv1 = 1.0f / lr_[1];
    const int srow = q0 + warp * 16 + myrow;
    #pragma unroll
    for (int j = 0; j < 16; j++) {
        int col = j * 8 + mycol;
        #pragma unroll
        for (int rr = 0; rr < 2; rr++) {
            float v0 = o[j][rr * 2]     * (rr ? inv1 : inv0);
            float v1 = o[j][rr * 2 + 1] * (rr ? inv1 : inv0);
            size_t off = ((size_t)(b * S_) + srow + rr * 8) * H_ + h * HD + col;
            __nv_bfloat16 h0 = __float2bfloat16(v0);
            __nv_bfloat16 h1 = __float2bfloat16(v1);
            *(__nv_bfloat162*)&g_ch[off] = __nv_bfloat162(h0, h1);
            *(__nv_bfloat162*)&g_cl[off] = __nv_bfloat162(
                __float2bfloat16(v0 - __bfloat162float(h0)),
                __float2bfloat16(v1 - __bfloat162float(h1)));
        }
    }
}

// ---------------------------------------------------------------------------
extern "C" void kernel_launch(void* const* d_in, const int* in_sizes, int n_in,
                              void* d_out, int out_size)
{
    (void)in_sizes; (void)n_in; (void)out_size;
    const float* x  = (const float*)d_in[0];
    const float* W[4] = { (const float*)d_in[1], (const float*)d_in[2],
                          (const float*)d_in[3], (const float*)d_in[4] };
    const float* cs = (const float*)d_in[5];
    const float* sn = (const float*)d_in[6];
    float* out = (float*)d_out;

    void *pxh, *pxl, *pwh, *pwl;
    cudaGetSymbolAddress(&pxh, g_xh);
    cudaGetSymbolAddress(&pxl, g_xl);
    cudaGetSymbolAddress(&pwh, g_wh);
    cudaGetSymbolAddress(&pwl, g_wl);

    // 0. Split inputs to bf16 hi/lo
    {
        int n4 = MTOT * H_ / 4;
        split_kernel<<<(n4 + 255) / 256, 256>>>(x, (__nv_bfloat16*)pxh,
                                                (__nv_bfloat16*)pxl, n4);
        int w4 = H_ * H_ / 4;
        for (int w = 0; w < 4; w++)
            split_kernel<<<(w4 + 255) / 256, 256>>>(
                W[w],
                (__nv_bfloat16*)pwh + (size_t)w * H_ * H_,
                (__nv_bfloat16*)pwl + (size_t)w * H_ * H_, w4);
    }

    // 1. Q/K/V projections (split-bf16 mma.sync, RoPE fused, fp16 hi/lo out)
    cudaFuncSetAttribute(qkv_mma_kernel,
                         cudaFuncAttributeMaxDynamicSharedMemorySize, GEMM_SMEM);
    qkv_mma_kernel<<<dim3(H_ / 128, MTOT / 128, 3), 256, GEMM_SMEM>>>(cs, sn);

    // 2. Tensor-core causal flash attention (split-fp16 QK)
    cudaFuncSetAttribute(attn_mma_kernel,
                         cudaFuncAttributeMaxDynamicSharedMemorySize, ATTN_SMEM);
    attn_mma_kernel<<<dim3(S_ / 128, B_ * NH), 256, ATTN_SMEM>>>();

    // 3. Output projection (split-bf16 mma.sync)
    cudaFuncSetAttribute(outproj_mma_kernel,
                         cudaFuncAttributeMaxDynamicSharedMemorySize, GEMM_SMEM);
    outproj_mma_kernel<<<dim3(H_ / 128, MTOT / 128), 256, GEMM_SMEM>>>(out);
}

// round 6
// speedup vs baseline: 1.8447x; 1.0307x over previous
#include <cuda_runtime.h>
#include <cuda_bf16.h>
#include <cuda_fp16.h>
#include <cstdint>

#define B_    2
#define S_    2048
#define H_    2048
#define NH    16
#define HD    128
#define MTOT  (B_ * S_)           // 4096
#define SCALE 11.313708498984761f // sqrt(128)

// GEMM tiling
#define BK      32
#define NCH     (H_ / BK)
#define TSTRIDE 40
#define TILE_B  (128 * TSTRIDE * 2)
#define BUF_B   (4 * TILE_B)
#define GEMM_SMEM (2 * BUF_B)        // 81920 B (2 CTAs/SM -> 160 KB)

// Attention smem: 6 half tiles [128][136]
#define AST 136
#define ATILE (128 * AST)
#define ATTN_SMEM (6 * ATILE * 2)    // 208896 B

// ---------------------------------------------------------------------------
// Device scratch
// ---------------------------------------------------------------------------
__device__ __nv_bfloat16 g_xh[(size_t)MTOT * H_];
__device__ __nv_bfloat16 g_xl[(size_t)MTOT * H_];
__device__ __nv_bfloat16 g_wh[4ull * H_ * H_];
__device__ __nv_bfloat16 g_wl[4ull * H_ * H_];
__device__ __nv_bfloat16 g_ch[(size_t)MTOT * H_];
__device__ __nv_bfloat16 g_cl[(size_t)MTOT * H_];
__device__ __half g_qh[(size_t)MTOT * H_];
__device__ __half g_ql[(size_t)MTOT * H_];
__device__ __half g_kh[(size_t)MTOT * H_];
__device__ __half g_kl[(size_t)MTOT * H_];
__device__ __half g_vh[(size_t)MTOT * H_];
__device__ __half g_vl[(size_t)MTOT * H_];

// ---------------------------------------------------------------------------
// PTX helpers
// ---------------------------------------------------------------------------
__device__ __forceinline__ uint32_t smem_u32(const void* p) {
    uint32_t a;
    asm("{ .reg .u64 t; cvta.to.shared.u64 t, %1; cvt.u32.u64 %0, t; }"
        : "=r"(a) : "l"(p));
    return a;
}

#define LDSM4(r, a) \
    asm volatile("ldmatrix.sync.aligned.m8n8.x4.shared.b16 {%0,%1,%2,%3}, [%4];" \
        : "=r"((r)[0]), "=r"((r)[1]), "=r"((r)[2]), "=r"((r)[3]) : "r"(a))
#define LDSM4T(r, a) \
    asm volatile("ldmatrix.sync.aligned.m8n8.x4.trans.shared.b16 {%0,%1,%2,%3}, [%4];" \
        : "=r"((r)[0]), "=r"((r)[1]), "=r"((r)[2]), "=r"((r)[3]) : "r"(a))

#define MMAB(d, a, b0v, b1v) \
    asm volatile("mma.sync.aligned.m16n8k16.row.col.f32.bf16.bf16.f32 " \
        "{%0,%1,%2,%3},{%4,%5,%6,%7},{%8,%9},{%0,%1,%2,%3};" \
        : "+f"((d)[0]), "+f"((d)[1]), "+f"((d)[2]), "+f"((d)[3]) \
        : "r"((a)[0]), "r"((a)[1]), "r"((a)[2]), "r"((a)[3]), \
          "r"(b0v), "r"(b1v))
#define MMAH(d, a, b0v, b1v) \
    asm volatile("mma.sync.aligned.m16n8k16.row.col.f32.f16.f16.f32 " \
        "{%0,%1,%2,%3},{%4,%5,%6,%7},{%8,%9},{%0,%1,%2,%3};" \
        : "+f"((d)[0]), "+f"((d)[1]), "+f"((d)[2]), "+f"((d)[3]) \
        : "r"((a)[0]), "r"((a)[1]), "r"((a)[2]), "r"((a)[3]), \
          "r"(b0v), "r"(b1v))

#define CPA16(dst, src) \
    asm volatile("cp.async.cg.shared.global [%0], [%1], 16;" \
        :: "r"(dst), "l"(src) : "memory")
#define CPA_COMMIT() asm volatile("cp.async.commit_group;" ::: "memory")
#define CPA_WAIT1()  asm volatile("cp.async.wait_group 1;" ::: "memory")
#define CPA_WAIT0()  asm volatile("cp.async.wait_group 0;" ::: "memory")

// ---------------------------------------------------------------------------
// Split-bf16 GEMM: term-major MMA ordering (dependency distance 4),
// reduced live registers (per-nb B fragments) -> 2 CTAs/SM.
// ---------------------------------------------------------------------------
__device__ __forceinline__ void prefetch_chunk(
    uint32_t sdst, const char* s0, const char* s1,
    const char* s2, const char* s3, int kc)
{
    const char* srcs[4] = { s0, s1, s2, s3 };
    const int tid = threadIdx.x;
    #pragma unroll
    for (int it = 0; it < 8; it++) {
        int idx  = it * 256 + tid;
        int tile = idx >> 9;
        int r    = (idx >> 2) & 127;
        int cv   = idx & 3;
        const char* src = srcs[tile] + (size_t)r * (H_ * 2) + kc * (BK * 2) + cv * 16;
        uint32_t dst = sdst + tile * TILE_B + (uint32_t)(r * TSTRIDE + cv * 8) * 2;
        CPA16(dst, src);
    }
    CPA_COMMIT();
}

__device__ __forceinline__ void gemm_main(
    const __nv_bfloat16* __restrict__ Ah, const __nv_bfloat16* __restrict__ Al,
    const __nv_bfloat16* __restrict__ Wh, const __nv_bfloat16* __restrict__ Wl,
    int m0, int n0, float acc[2][8][4])
{
    extern __shared__ char smx[];
    const uint32_t sbase = smem_u32(smx);
    const char* a0 = (const char*)(Ah + (size_t)m0 * H_);
    const char* a1 = (const char*)(Al + (size_t)m0 * H_);
    const char* b0 = (const char*)(Wh + (size_t)n0 * H_);
    const char* b1 = (const char*)(Wl + (size_t)n0 * H_);
    const int lane = threadIdx.x & 31;
    const int warp = threadIdx.x >> 5;
    const int wm = warp & 3;
    const int wn = warp >> 2;
    const int lrow = lane & 15;
    const int lk8  = (lane >> 4) * 8;

    prefetch_chunk(sbase, a0, a1, b0, b1, 0);

    for (int c = 0; c < NCH; c++) {
        const uint32_t sbuf = sbase + (uint32_t)(c & 1) * BUF_B;
        if (c + 1 < NCH) {
            prefetch_chunk(sbase + (uint32_t)((c + 1) & 1) * BUF_B,
                           a0, a1, b0, b1, c + 1);
            CPA_WAIT1();
        } else {
            CPA_WAIT0();
        }
        __syncthreads();

        #pragma unroll
        for (int ks = 0; ks < 2; ks++) {
            const int koff = ks * 16 + lk8;
            uint32_t ah[2][4], al[2][4];
            #pragma unroll
            for (int g = 0; g < 2; g++) {
                uint32_t addr = sbuf +
                    (uint32_t)((wm * 32 + g * 16 + lrow) * TSTRIDE + koff) * 2;
                LDSM4(ah[g], addr);
                LDSM4(al[g], addr + TILE_B);
            }
            #pragma unroll
            for (int nb = 0; nb < 4; nb++) {
                uint32_t addr = sbuf + 2 * TILE_B +
                    (uint32_t)((wn * 64 + nb * 16 + lrow) * TSTRIDE + koff) * 2;
                uint32_t bh[4], bl[4];
                LDSM4(bh, addr);
                LDSM4(bl, addr + TILE_B);
                // term-major: dependent pairs (same acc) are 4 apart
                MMAB(acc[0][2*nb],   ah[0], bh[0], bh[2]);
                MMAB(acc[0][2*nb+1], ah[0], bh[1], bh[3]);
                MMAB(acc[1][2*nb],   ah[1], bh[0], bh[2]);
                MMAB(acc[1][2*nb+1], ah[1], bh[1], bh[3]);

                MMAB(acc[0][2*nb],   ah[0], bl[0], bl[2]);
                MMAB(acc[0][2*nb+1], ah[0], bl[1], bl[3]);
                MMAB(acc[1][2*nb],   ah[1], bl[0], bl[2]);
                MMAB(acc[1][2*nb+1], ah[1], bl[1], bl[3]);

                MMAB(acc[0][2*nb],   al[0], bh[0], bh[2]);
                MMAB(acc[0][2*nb+1], al[0], bh[1], bh[3]);
                MMAB(acc[1][2*nb],   al[1], bh[0], bh[2]);
                MMAB(acc[1][2*nb+1], al[1], bh[1], bh[3]);
            }
        }
        __syncthreads();
    }
}

__device__ __forceinline__ void acc_to_smem(float acc[2][8][4], float* smf)
{
    const int lane = threadIdx.x & 31;
    const int warp = threadIdx.x >> 5;
    const int wm = warp & 3, wn = warp >> 2;
    #pragma unroll
    for (int g = 0; g < 2; g++) {
        #pragma unroll
        for (int j = 0; j < 8; j++) {
            int row = wm * 32 + g * 16 + (lane >> 2);
            int col = wn * 64 + (j >> 1) * 16 + (j & 1) * 8 + 2 * (lane & 3);
            smf[row * 132 + col]           = acc[g][j][0];
            smf[row * 132 + col + 1]       = acc[g][j][1];
            smf[(row + 8) * 132 + col]     = acc[g][j][2];
            smf[(row + 8) * 132 + col + 1] = acc[g][j][3];
        }
    }
}

// ---------------------------------------------------------------------------
// QKV projection; RoPE fused; writes Q,K,V all as fp16 hi/lo.
// ---------------------------------------------------------------------------
__global__ __launch_bounds__(256, 2)
void qkv_mma_kernel(const float* __restrict__ cs, const float* __restrict__ sn)
{
    const int z    = blockIdx.z;
    const int head = blockIdx.x;
    const int m0   = blockIdx.y * 128;
    const int n0   = head * 128;

    float acc[2][8][4];
    #pragma unroll
    for (int g = 0; g < 2; g++)
        #pragma unroll
        for (int j = 0; j < 8; j++)
            #pragma unroll
            for (int e = 0; e < 4; e++) acc[g][j][e] = 0.f;

    gemm_main(g_xh, g_xl,
              g_wh + (size_t)z * H_ * H_,
              g_wl + (size_t)z * H_ * H_, m0, n0, acc);

    extern __shared__ char smx[];
    float* smf = (float*)smx;
    acc_to_smem(acc, smf);
    __syncthreads();

    const int t  = threadIdx.x;
    const int r  = t >> 1;
    const int dh = (t & 1) * 32;
    const int m  = m0 + r;
    const int s  = m & (S_ - 1);
    const int b  = m >> 11;
    const size_t rowbase = ((size_t)(b * NH + head) * S_ + s) * HD;

    __half* dsth = (z == 0) ? g_qh : (z == 1) ? g_kh : g_vh;
    __half* dstl = (z == 0) ? g_ql : (z == 1) ? g_kl : g_vl;
    dsth += rowbase;
    dstl += rowbase;

    if (z < 2) {
        const float* crow = cs + (size_t)s * HD;
        const float* srow = sn + (size_t)s * HD;
        #pragma unroll
        for (int j = 0; j < 32; j++) {
            float lo = smf[r * 132 + dh + j];
            float hi = smf[r * 132 + dh + j + 64];
            float olo = lo * crow[dh + j]      - hi * srow[dh + j];
            float ohi = hi * crow[dh + j + 64] + lo * srow[dh + j + 64];
            __half a = __float2half_rn(olo);
            __half bq = __float2half_rn(ohi);
            dsth[dh + j]      = a;
            dsth[dh + j + 64] = bq;
            dstl[dh + j]      = __float2half_rn(olo - __half2float(a));
            dstl[dh + j + 64] = __float2half_rn(ohi - __half2float(bq));
        }
    } else {
        #pragma unroll
        for (int j = 0; j < 32; j++) {
            #pragma unroll
            for (int half_ = 0; half_ < 2; half_++) {
                int cc = dh + j + half_ * 64;
                float v = smf[r * 132 + cc];
                __half vh = __float2half_rn(v);
                dsth[cc] = vh;
                dstl[cc] = __float2half_rn(v - __half2float(vh));
            }
        }
    }
}

// ---------------------------------------------------------------------------
// Output projection
// ---------------------------------------------------------------------------
__global__ __launch_bounds__(256, 2)
void outproj_mma_kernel(float* __restrict__ out)
{
    const int m0 = blockIdx.y * 128;
    const int n0 = blockIdx.x * 128;

    float acc[2][8][4];
    #pragma unroll
    for (int g = 0; g < 2; g++)
        #pragma unroll
        for (int j = 0; j < 8; j++)
            #pragma unroll
            for (int e = 0; e < 4; e++) acc[g][j][e] = 0.f;

    gemm_main(g_ch, g_cl,
              g_wh + 3ull * H_ * H_,
              g_wl + 3ull * H_ * H_, m0, n0, acc);

    const int lane = threadIdx.x & 31;
    const int warp = threadIdx.x >> 5;
    const int wm = warp & 3, wn = warp >> 2;
    #pragma unroll
    for (int g = 0; g < 2; g++) {
        #pragma unroll
        for (int j = 0; j < 8; j++) {
            size_t row = (size_t)m0 + wm * 32 + g * 16 + (lane >> 2);
            int col = n0 + wn * 64 + (j >> 1) * 16 + (j & 1) * 8 + 2 * (lane & 3);
            *(float2*)&out[row * H_ + col] =
                make_float2(acc[g][j][0], acc[g][j][1]);
            *(float2*)&out[(row + 8) * H_ + col] =
                make_float2(acc[g][j][2], acc[g][j][3]);
        }
    }
}

// ---------------------------------------------------------------------------
// fp32 -> bf16 hi/lo split
// ---------------------------------------------------------------------------
__global__ void split_kernel(const float* __restrict__ src,
                             __nv_bfloat16* __restrict__ hi,
                             __nv_bfloat16* __restrict__ lo, int n4)
{
    int i = blockIdx.x * blockDim.x + threadIdx.x;
    if (i >= n4) return;
    float4 v = ((const float4*)src)[i];
    __nv_bfloat16 h0 = __float2bfloat16(v.x), h1 = __float2bfloat16(v.y);
    __nv_bfloat16 h2 = __float2bfloat16(v.z), h3 = __float2bfloat16(v.w);
    __nv_bfloat16 l0 = __float2bfloat16(v.x - __bfloat162float(h0));
    __nv_bfloat16 l1 = __float2bfloat16(v.y - __bfloat162float(h1));
    __nv_bfloat16 l2 = __float2bfloat16(v.z - __bfloat162float(h2));
    __nv_bfloat16 l3 = __float2bfloat16(v.w - __bfloat162float(h3));
    ((__nv_bfloat162*)hi)[2*i]   = __nv_bfloat162(h0, h1);
    ((__nv_bfloat162*)hi)[2*i+1] = __nv_bfloat162(h2, h3);
    ((__nv_bfloat162*)lo)[2*i]   = __nv_bfloat162(l0, l1);
    ((__nv_bfloat162*)lo)[2*i+1] = __nv_bfloat162(l2, l3);
}

// ---------------------------------------------------------------------------
// Tensor-core causal flash attention (split-fp16 QK^T, split-fp16 PV).
// MMAs grouped in pairs (jj / dd) with term-major order -> dep distance 4.
// ---------------------------------------------------------------------------
__global__ __launch_bounds__(256, 1)
void attn_mma_kernel()
{
    extern __shared__ char smem[];
    __half* sQh = (__half*)smem;
    __half* sQl = sQh + ATILE;
    __half* sKh = sQl + ATILE;
    __half* sKl = sKh + ATILE;
    __half* sVh = sKl + ATILE;
    __half* sVl = sVh + ATILE;

    const int tid  = threadIdx.x;
    const int lane = tid & 31;
    const int warp = tid >> 5;
    const int lrow = lane & 7;
    const int lq   = lane >> 3;
    const int qt   = (gridDim.x - 1) - blockIdx.x;
    const int bh   = blockIdx.y;
    const int q0   = qt * 128;
    const size_t base = (size_t)bh * S_ * HD;

    const uint32_t sQh_u = smem_u32(sQh);
    const uint32_t sQl_u = smem_u32(sQl);
    const uint32_t sKh_u = smem_u32(sKh);
    const uint32_t sKl_u = smem_u32(sKl);
    const uint32_t sVh_u = smem_u32(sVh);
    const uint32_t sVl_u = smem_u32(sVl);

    #pragma unroll
    for (int it = 0; it < 8; it++) {
        int idx = it * 256 + tid;
        int r   = idx >> 4;
        int c8  = (idx & 15) * 8;
        size_t g = base + (size_t)(q0 + r) * HD + c8;
        uint32_t so = (uint32_t)(r * AST + c8) * 2;
        CPA16(sQh_u + so, (const char*)&g_qh[g]);
        CPA16(sQl_u + so, (const char*)&g_ql[g]);
    }
    CPA_COMMIT();
    CPA_WAIT0();
    __syncthreads();

    uint32_t qfh[8][4], qfl[8][4];
    {
        int row = warp * 16 + ((lq & 1) ? 8 : 0) + lrow;
        #pragma unroll
        for (int ks = 0; ks < 8; ks++) {
            int col = ks * 16 + ((lq & 2) ? 8 : 0);
            uint32_t so = (uint32_t)(row * AST + col) * 2;
            LDSM4(qfh[ks], sQh_u + so);
            LDSM4(qfl[ks], sQl_u + so);
        }
    }

    float o[16][4];
    #pragma unroll
    for (int j = 0; j < 16; j++)
        #pragma unroll
        for (int e = 0; e < 4; e++) o[j][e] = 0.f;
    float mr[2] = { -1e30f, -1e30f };
    float lr_[2] = { 0.f, 0.f };

    const int krow_b = ((lq & 2) ? 8 : 0) + lrow;
    const int kcol_b = ((lq & 1) ? 8 : 0);
    const int vrow_b = ((lq & 1) ? 8 : 0) + lrow;
    const int vcol_b = ((lq & 2) ? 8 : 0);
    const int myrow  = lane >> 2;
    const int mycol  = 2 * (lane & 3);

    for (int kt = 0; kt <= qt; kt++) {
        const int kb = kt * 128;
        __syncthreads();

        #pragma unroll
        for (int it = 0; it < 8; it++) {
            int idx = it * 256 + tid;
            int r   = idx >> 4;
            int c8  = (idx & 15) * 8;
            size_t g = base + (size_t)(kb + r) * HD + c8;
            uint32_t so = (uint32_t)(r * AST + c8) * 2;
            CPA16(sKh_u + so, (const char*)&g_kh[g]);
            CPA16(sKl_u + so, (const char*)&g_kl[g]);
            CPA16(sVh_u + so, (const char*)&g_vh[g]);
            CPA16(sVl_u + so, (const char*)&g_vl[g]);
        }
        CPA_COMMIT();
        CPA_WAIT0();
        __syncthreads();

        // ---- S = Qh Kh^T + Qh Kl^T + Ql Kh^T ----
        float sf[16][4];
        #pragma unroll
        for (int j = 0; j < 16; j++)
            #pragma unroll
            for (int e = 0; e < 4; e++) sf[j][e] = 0.f;

        #pragma unroll
        for (int ks = 0; ks < 8; ks++) {
            #pragma unroll
            for (int jj = 0; jj < 8; jj += 2) {
                int col = ks * 16 + kcol_b;
                uint32_t so0 = (uint32_t)(((jj    ) * 16 + krow_b) * AST + col) * 2;
                uint32_t so1 = (uint32_t)(((jj + 1) * 16 + krow_b) * AST + col) * 2;
                uint32_t kfh0[4], kfl0[4], kfh1[4], kfl1[4];
                LDSM4(kfh0, sKh_u + so0);
                LDSM4(kfh1, sKh_u + so1);
                LDSM4(kfl0, sKl_u + so0);
                LDSM4(kfl1, sKl_u + so1);
                // hh
                MMAH(sf[2*jj],   qfh[ks], kfh0[0], kfh0[1]);
                MMAH(sf[2*jj+1], qfh[ks], kfh0[2], kfh0[3]);
                MMAH(sf[2*jj+2], qfh[ks], kfh1[0], kfh1[1]);
                MMAH(sf[2*jj+3], qfh[ks], kfh1[2], kfh1[3]);
                // hl
                MMAH(sf[2*jj],   qfh[ks], kfl0[0], kfl0[1]);
                MMAH(sf[2*jj+1], qfh[ks], kfl0[2], kfl0[3]);
                MMAH(sf[2*jj+2], qfh[ks], kfl1[0], kfl1[1]);
                MMAH(sf[2*jj+3], qfh[ks], kfl1[2], kfl1[3]);
                // lh
                MMAH(sf[2*jj],   qfl[ks], kfh0[0], kfh0[1]);
                MMAH(sf[2*jj+1], qfl[ks], kfh0[2], kfh0[3]);
                MMAH(sf[2*jj+2], qfl[ks], kfh1[0], kfh1[1]);
                MMAH(sf[2*jj+3], qfl[ks], kfh1[2], kfh1[3]);
            }
        }

        // ---- online softmax ----
        const bool diag = (kt == qt);
        const int grow0 = q0 + warp * 16 + myrow;
        #pragma unroll
        for (int rr = 0; rr < 2; rr++) {
            const int grow = grow0 + rr * 8;
            float mx = -1e30f;
            #pragma unroll
            for (int j = 0; j < 16; j++) {
                #pragma unroll
                for (int e = 0; e < 2; e++) {
                    float v = sf[j][rr * 2 + e] * SCALE;
                    if (diag && (kb + j * 8 + mycol + e) > grow) v = -1e30f;
                    sf[j][rr * 2 + e] = v;
                    mx = fmaxf(mx, v);
                }
            }
            mx = fmaxf(mx, __shfl_xor_sync(0xffffffffu, mx, 1));
            mx = fmaxf(mx, __shfl_xor_sync(0xffffffffu, mx, 2));
            float mnew  = fmaxf(mr[rr], mx);
            float alpha = __expf(mr[rr] - mnew);
            mr[rr] = mnew;
            float ls = 0.f;
            #pragma unroll
            for (int j = 0; j < 16; j++) {
                #pragma unroll
                for (int e = 0; e < 2; e++) {
                    float p = __expf(sf[j][rr * 2 + e] - mnew);
                    sf[j][rr * 2 + e] = p;
                    ls += p;
                }
            }
            ls += __shfl_xor_sync(0xffffffffu, ls, 1);
            ls += __shfl_xor_sync(0xffffffffu, ls, 2);
            lr_[rr] = lr_[rr] * alpha + ls;
            #pragma unroll
            for (int j = 0; j < 16; j++) {
                o[j][rr * 2]     *= alpha;
                o[j][rr * 2 + 1] *= alpha;
            }
        }

        // ---- pack P to fp16 A-frags ----
        uint32_t pf[8][4];
        #pragma unroll
        for (int j = 0; j < 8; j++) {
            __half2 h;
            h = __floats2half2_rn(sf[2*j][0],   sf[2*j][1]);   pf[j][0] = *(uint32_t*)&h;
            h = __floats2half2_rn(sf[2*j][2],   sf[2*j][3]);   pf[j][1] = *(uint32_t*)&h;
            h = __floats2half2_rn(sf[2*j+1][0], sf[2*j+1][1]); pf[j][2] = *(uint32_t*)&h;
            h = __floats2half2_rn(sf[2*j+1][2], sf[2*j+1][3]); pf[j][3] = *(uint32_t*)&h;
        }

        // ---- O += P (Vh + Vl), dd-pairs, term-major ----
        #pragma unroll
        for (int j = 0; j < 8; j++) {
            int row = j * 16 + vrow_b;
            #pragma unroll
            for (int dd = 0; dd < 8; dd += 2) {
                uint32_t so0 = (uint32_t)(row * AST + (dd    ) * 16 + vcol_b) * 2;
                uint32_t so1 = (uint32_t)(row * AST + (dd + 1) * 16 + vcol_b) * 2;
                uint32_t vh0[4], vl0[4], vh1[4], vl1[4];
                LDSM4T(vh0, sVh_u + so0);
                LDSM4T(vh1, sVh_u + so1);
                LDSM4T(vl0, sVl_u + so0);
                LDSM4T(vl1, sVl_u + so1);
                MMAH(o[2*dd],   pf[j], vh0[0], vh0[1]);
                MMAH(o[2*dd+1], pf[j], vh0[2], vh0[3]);
                MMAH(o[2*dd+2], pf[j], vh1[0], vh1[1]);
                MMAH(o[2*dd+3], pf[j], vh1[2], vh1[3]);
                MMAH(o[2*dd],   pf[j], vl0[0], vl0[1]);
                MMAH(o[2*dd+1], pf[j], vl0[2], vl0[3]);
                MMAH(o[2*dd+2], pf[j], vl1[0], vl1[1]);
                MMAH(o[2*dd+3], pf[j], vl1[2], vl1[3]);
            }
        }
    }

    // ---- epilogue ----
    const int b = bh >> 4;
    const int h = bh & 15;
    float inv0 = 1.0f / lr_[0];
    float inv1 = 1.0f / lr_[1];
    const int srow = q0 + warp * 16 + myrow;
    #pragma unroll
    for (int j = 0; j < 16; j++) {
        int col = j * 8 + mycol;
        #pragma unroll
        for (int rr = 0; rr < 2; rr++) {
            float v0 = o[j][rr * 2]     * (rr ? inv1 : inv0);
            float v1 = o[j][rr * 2 + 1] * (rr ? inv1 : inv0);
            size_t off = ((size_t)(b * S_) + srow + rr * 8) * H_ + h * HD + col;
            __nv_bfloat16 h0 = __float2bfloat16(v0);
            __nv_bfloat16 h1 = __float2bfloat16(v1);
            *(__nv_bfloat162*)&g_ch[off] = __nv_bfloat162(h0, h1);
            *(__nv_bfloat162*)&g_cl[off] = __nv_bfloat162(
                __float2bfloat16(v0 - __bfloat162float(h0)),
                __float2bfloat16(v1 - __bfloat162float(h1)));
        }
    }
}

// ---------------------------------------------------------------------------
extern "C" void kernel_launch(void* const* d_in, const int* in_sizes, int n_in,
                              void* d_out, int out_size)
{
    (void)in_sizes; (void)n_in; (void)out_size;
    const float* x  = (const float*)d_in[0];
    const float* W[4] = { (const float*)d_in[1], (const float*)d_in[2],
                          (const float*)d_in[3], (const float*)d_in[4] };
    const float* cs = (const float*)d_in[5];
    const float* sn = (const float*)d_in[6];
    float* out = (float*)d_out;

    void *pxh, *pxl, *pwh, *pwl;
    cudaGetSymbolAddress(&pxh, g_xh);
    cudaGetSymbolAddress(&pxl, g_xl);
    cudaGetSymbolAddress(&pwh, g_wh);
    cudaGetSymbolAddress(&pwl, g_wl);

    {
        int n4 = MTOT * H_ / 4;
        split_kernel<<<(n4 + 255) / 256, 256>>>(x, (__nv_bfloat16*)pxh,
                                                (__nv_bfloat16*)pxl, n4);
        int w4 = H_ * H_ / 4;
        for (int w = 0; w < 4; w++)
            split_kernel<<<(w4 + 255) / 256, 256>>>(
                W[w],
                (__nv_bfloat16*)pwh + (size_t)w * H_ * H_,
                (__nv_bfloat16*)pwl + (size_t)w * H_ * H_, w4);
    }

    cudaFuncSetAttribute(qkv_mma_kernel,
                         cudaFuncAttributeMaxDynamicSharedMemorySize, GEMM_SMEM);
    qkv_mma_kernel<<<dim3(H_ / 128, MTOT / 128, 3), 256, GEMM_SMEM>>>(cs, sn);

    cudaFuncSetAttribute(attn_mma_kernel,
                         cudaFuncAttributeMaxDynamicSharedMemorySize, ATTN_SMEM);
    attn_mma_kernel<<<dim3(S_ / 128, B_ * NH), 256, ATTN_SMEM>>>();

    cudaFuncSetAttribute(outproj_mma_kernel,
                         cudaFuncAttributeMaxDynamicSharedMemorySize, GEMM_SMEM);
    outproj_mma_kernel<<<dim3(H_ / 128, MTOT / 128), 256, GEMM_SMEM>>>(out);
}

// round 7
// speedup vs baseline: 2.5373x; 1.3755x over previous
#include <cuda_runtime.h>
#include <cuda_bf16.h>
#include <cuda_fp16.h>
#include <cstdint>

#define B_    2
#define S_    2048
#define H_    2048
#define NH    16
#define HD    128
#define MTOT  (B_ * S_)           // 4096
#define SCALE 11.313708498984761f // sqrt(128)
#define HH    ((size_t)H_ * H_)

// GEMM tiling
#define BK      32
#define NCH     (H_ / BK)
#define TSTRIDE 40
#define TILE_B  (128 * TSTRIDE * 2)   // 10240 B
#define BUF_B   (4 * TILE_B)          // 3-term: Ah,Al,Wh,Wl
#define BUF1_B  (2 * TILE_B)          // 1-term: A,W
#define GEMM_SMEM (2 * BUF_B)         // 81920 B
#define OUT_SMEM  (2 * BUF1_B)        // 40960 B

// Attention smem: 5 half tiles [128][136] (Qh,Ql,Kh,Kl,Vh)
#define AST 136
#define ATILE (128 * AST)
#define ATTN_SMEM (5 * ATILE * 2)     // 174080 B

// ---------------------------------------------------------------------------
// Device scratch
// ---------------------------------------------------------------------------
__device__ __nv_bfloat16 g_xh[(size_t)MTOT * H_];   // x bf16 hi/lo (Q,K proj)
__device__ __nv_bfloat16 g_xl[(size_t)MTOT * H_];
__device__ __nv_bfloat16 g_wh[2ull * HH];           // Wq,Wk bf16 hi/lo
__device__ __nv_bfloat16 g_wl[2ull * HH];
__device__ __half g_xf [(size_t)MTOT * H_];         // x fp16 (V proj)
__device__ __half g_wvf[HH];                        // Wv fp16
__device__ __half g_wof[HH];                        // Wo fp16
__device__ __half g_cf [(size_t)MTOT * H_];         // ctx fp16
__device__ __half g_qh[(size_t)MTOT * H_];          // q fp16 hi/lo (post-RoPE)
__device__ __half g_ql[(size_t)MTOT * H_];
__device__ __half g_kh[(size_t)MTOT * H_];
__device__ __half g_kl[(size_t)MTOT * H_];
__device__ __half g_vh[(size_t)MTOT * H_];          // v fp16 single

// ---------------------------------------------------------------------------
// PTX helpers
// ---------------------------------------------------------------------------
__device__ __forceinline__ uint32_t smem_u32(const void* p) {
    uint32_t a;
    asm("{ .reg .u64 t; cvta.to.shared.u64 t, %1; cvt.u32.u64 %0, t; }"
        : "=r"(a) : "l"(p));
    return a;
}

#define LDSM4(r, a) \
    asm volatile("ldmatrix.sync.aligned.m8n8.x4.shared.b16 {%0,%1,%2,%3}, [%4];" \
        : "=r"((r)[0]), "=r"((r)[1]), "=r"((r)[2]), "=r"((r)[3]) : "r"(a))
#define LDSM4T(r, a) \
    asm volatile("ldmatrix.sync.aligned.m8n8.x4.trans.shared.b16 {%0,%1,%2,%3}, [%4];" \
        : "=r"((r)[0]), "=r"((r)[1]), "=r"((r)[2]), "=r"((r)[3]) : "r"(a))

#define MMAB(d, a, b0v, b1v) \
    asm volatile("mma.sync.aligned.m16n8k16.row.col.f32.bf16.bf16.f32 " \
        "{%0,%1,%2,%3},{%4,%5,%6,%7},{%8,%9},{%0,%1,%2,%3};" \
        : "+f"((d)[0]), "+f"((d)[1]), "+f"((d)[2]), "+f"((d)[3]) \
        : "r"((a)[0]), "r"((a)[1]), "r"((a)[2]), "r"((a)[3]), \
          "r"(b0v), "r"(b1v))
#define MMAH(d, a, b0v, b1v) \
    asm volatile("mma.sync.aligned.m16n8k16.row.col.f32.f16.f16.f32 " \
        "{%0,%1,%2,%3},{%4,%5,%6,%7},{%8,%9},{%0,%1,%2,%3};" \
        : "+f"((d)[0]), "+f"((d)[1]), "+f"((d)[2]), "+f"((d)[3]) \
        : "r"((a)[0]), "r"((a)[1]), "r"((a)[2]), "r"((a)[3]), \
          "r"(b0v), "r"(b1v))

#define CPA16(dst, src) \
    asm volatile("cp.async.cg.shared.global [%0], [%1], 16;" \
        :: "r"(dst), "l"(src) : "memory")
#define CPA_COMMIT() asm volatile("cp.async.commit_group;" ::: "memory")
#define CPA_WAIT1()  asm volatile("cp.async.wait_group 1;" ::: "memory")
#define CPA_WAIT0()  asm volatile("cp.async.wait_group 0;" ::: "memory")

// ---------------------------------------------------------------------------
// 3-term split-bf16 GEMM (Q,K projections) — unchanged from R6
// ---------------------------------------------------------------------------
__device__ __forceinline__ void prefetch4(
    uint32_t sdst, const char* s0, const char* s1,
    const char* s2, const char* s3, int kc)
{
    const char* srcs[4] = { s0, s1, s2, s3 };
    const int tid = threadIdx.x;
    #pragma unroll
    for (int it = 0; it < 8; it++) {
        int idx  = it * 256 + tid;
        int tile = idx >> 9;
        int r    = (idx >> 2) & 127;
        int cv   = idx & 3;
        const char* src = srcs[tile] + (size_t)r * (H_ * 2) + kc * (BK * 2) + cv * 16;
        uint32_t dst = sdst + tile * TILE_B + (uint32_t)(r * TSTRIDE + cv * 8) * 2;
        CPA16(dst, src);
    }
    CPA_COMMIT();
}

__device__ __forceinline__ void gemm_main3(
    const __nv_bfloat16* __restrict__ Ah, const __nv_bfloat16* __restrict__ Al,
    const __nv_bfloat16* __restrict__ Wh, const __nv_bfloat16* __restrict__ Wl,
    int m0, int n0, float acc[2][8][4])
{
    extern __shared__ char smx[];
    const uint32_t sbase = smem_u32(smx);
    const char* a0 = (const char*)(Ah + (size_t)m0 * H_);
    const char* a1 = (const char*)(Al + (size_t)m0 * H_);
    const char* b0 = (const char*)(Wh + (size_t)n0 * H_);
    const char* b1 = (const char*)(Wl + (size_t)n0 * H_);
    const int lane = threadIdx.x & 31;
    const int warp = threadIdx.x >> 5;
    const int wm = warp & 3;
    const int wn = warp >> 2;
    const int lrow = lane & 15;
    const int lk8  = (lane >> 4) * 8;

    prefetch4(sbase, a0, a1, b0, b1, 0);

    for (int c = 0; c < NCH; c++) {
        const uint32_t sbuf = sbase + (uint32_t)(c & 1) * BUF_B;
        if (c + 1 < NCH) {
            prefetch4(sbase + (uint32_t)((c + 1) & 1) * BUF_B, a0, a1, b0, b1, c + 1);
            CPA_WAIT1();
        } else {
            CPA_WAIT0();
        }
        __syncthreads();

        #pragma unroll
        for (int ks = 0; ks < 2; ks++) {
            const int koff = ks * 16 + lk8;
            uint32_t ah[2][4], al[2][4];
            #pragma unroll
            for (int g = 0; g < 2; g++) {
                uint32_t addr = sbuf +
                    (uint32_t)((wm * 32 + g * 16 + lrow) * TSTRIDE + koff) * 2;
                LDSM4(ah[g], addr);
                LDSM4(al[g], addr + TILE_B);
            }
            #pragma unroll
            for (int nb = 0; nb < 4; nb++) {
                uint32_t addr = sbuf + 2 * TILE_B +
                    (uint32_t)((wn * 64 + nb * 16 + lrow) * TSTRIDE + koff) * 2;
                uint32_t bh[4], bl[4];
                LDSM4(bh, addr);
                LDSM4(bl, addr + TILE_B);
                MMAB(acc[0][2*nb],   ah[0], bh[0], bh[2]);
                MMAB(acc[0][2*nb+1], ah[0], bh[1], bh[3]);
                MMAB(acc[1][2*nb],   ah[1], bh[0], bh[2]);
                MMAB(acc[1][2*nb+1], ah[1], bh[1], bh[3]);

                MMAB(acc[0][2*nb],   ah[0], bl[0], bl[2]);
                MMAB(acc[0][2*nb+1], ah[0], bl[1], bl[3]);
                MMAB(acc[1][2*nb],   ah[1], bl[0], bl[2]);
                MMAB(acc[1][2*nb+1], ah[1], bl[1], bl[3]);

                MMAB(acc[0][2*nb],   al[0], bh[0], bh[2]);
                MMAB(acc[0][2*nb+1], al[0], bh[1], bh[3]);
                MMAB(acc[1][2*nb],   al[1], bh[0], bh[2]);
                MMAB(acc[1][2*nb+1], al[1], bh[1], bh[3]);
            }
        }
        __syncthreads();
    }
}

// ---------------------------------------------------------------------------
// 1-term fp16 GEMM (V projection, output projection)
// ---------------------------------------------------------------------------
__device__ __forceinline__ void prefetch2(
    uint32_t sdst, const char* s0, const char* s1, int kc)
{
    const char* srcs[2] = { s0, s1 };
    const int tid = threadIdx.x;
    #pragma unroll
    for (int it = 0; it < 4; it++) {
        int idx  = it * 256 + tid;
        int tile = idx >> 9;
        int r    = (idx >> 2) & 127;
        int cv   = idx & 3;
        const char* src = srcs[tile] + (size_t)r * (H_ * 2) + kc * (BK * 2) + cv * 16;
        uint32_t dst = sdst + tile * TILE_B + (uint32_t)(r * TSTRIDE + cv * 8) * 2;
        CPA16(dst, src);
    }
    CPA_COMMIT();
}

__device__ __forceinline__ void gemm_main1(
    const __half* __restrict__ A, const __half* __restrict__ W,
    int m0, int n0, float acc[2][8][4])
{
    extern __shared__ char smx[];
    const uint32_t sbase = smem_u32(smx);
    const char* a0 = (const char*)(A + (size_t)m0 * H_);
    const char* b0 = (const char*)(W + (size_t)n0 * H_);
    const int lane = threadIdx.x & 31;
    const int warp = threadIdx.x >> 5;
    const int wm = warp & 3;
    const int wn = warp >> 2;
    const int lrow = lane & 15;
    const int lk8  = (lane >> 4) * 8;

    prefetch2(sbase, a0, b0, 0);

    for (int c = 0; c < NCH; c++) {
        const uint32_t sbuf = sbase + (uint32_t)(c & 1) * BUF1_B;
        if (c + 1 < NCH) {
            prefetch2(sbase + (uint32_t)((c + 1) & 1) * BUF1_B, a0, b0, c + 1);
            CPA_WAIT1();
        } else {
            CPA_WAIT0();
        }
        __syncthreads();

        #pragma unroll
        for (int ks = 0; ks < 2; ks++) {
            const int koff = ks * 16 + lk8;
            uint32_t ah[2][4];
            #pragma unroll
            for (int g = 0; g < 2; g++) {
                uint32_t addr = sbuf +
                    (uint32_t)((wm * 32 + g * 16 + lrow) * TSTRIDE + koff) * 2;
                LDSM4(ah[g], addr);
            }
            #pragma unroll
            for (int nb = 0; nb < 4; nb++) {
                uint32_t addr = sbuf + TILE_B +
                    (uint32_t)((wn * 64 + nb * 16 + lrow) * TSTRIDE + koff) * 2;
                uint32_t bh[4];
                LDSM4(bh, addr);
                MMAH(acc[0][2*nb],   ah[0], bh[0], bh[2]);
                MMAH(acc[0][2*nb+1], ah[0], bh[1], bh[3]);
                MMAH(acc[1][2*nb],   ah[1], bh[0], bh[2]);
                MMAH(acc[1][2*nb+1], ah[1], bh[1], bh[3]);
            }
        }
        __syncthreads();
    }
}

__device__ __forceinline__ void acc_to_smem(float acc[2][8][4], float* smf)
{
    const int lane = threadIdx.x & 31;
    const int warp = threadIdx.x >> 5;
    const int wm = warp & 3, wn = warp >> 2;
    #pragma unroll
    for (int g = 0; g < 2; g++) {
        #pragma unroll
        for (int j = 0; j < 8; j++) {
            int row = wm * 32 + g * 16 + (lane >> 2);
            int col = wn * 64 + (j >> 1) * 16 + (j & 1) * 8 + 2 * (lane & 3);
            smf[row * 132 + col]           = acc[g][j][0];
            smf[row * 132 + col + 1]       = acc[g][j][1];
            smf[(row + 8) * 132 + col]     = acc[g][j][2];
            smf[(row + 8) * 132 + col + 1] = acc[g][j][3];
        }
    }
}

// ---------------------------------------------------------------------------
// QKV projection. z<2: 3-term bf16 GEMM + RoPE -> q/k fp16 hi/lo.
//                 z=2: 1-term fp16 GEMM       -> v fp16 single.
// ---------------------------------------------------------------------------
__global__ __launch_bounds__(256, 2)
void qkv_mma_kernel(const float* __restrict__ cs, const float* __restrict__ sn)
{
    const int z    = blockIdx.z;
    const int head = blockIdx.x;
    const int m0   = blockIdx.y * 128;
    const int n0   = head * 128;

    float acc[2][8][4];
    #pragma unroll
    for (int g = 0; g < 2; g++)
        #pragma unroll
        for (int j = 0; j < 8; j++)
            #pragma unroll
            for (int e = 0; e < 4; e++) acc[g][j][e] = 0.f;

    if (z < 2) {
        gemm_main3(g_xh, g_xl, g_wh + (size_t)z * HH, g_wl + (size_t)z * HH,
                   m0, n0, acc);
    } else {
        gemm_main1(g_xf, g_wvf, m0, n0, acc);
    }

    extern __shared__ char smx[];
    float* smf = (float*)smx;
    acc_to_smem(acc, smf);
    __syncthreads();

    const int t  = threadIdx.x;
    const int r  = t >> 1;
    const int dh = (t & 1) * 32;
    const int m  = m0 + r;
    const int s  = m & (S_ - 1);
    const int b  = m >> 11;
    const size_t rowbase = ((size_t)(b * NH + head) * S_ + s) * HD;

    if (z < 2) {
        __half* dsth = ((z == 0) ? g_qh : g_kh) + rowbase;
        __half* dstl = ((z == 0) ? g_ql : g_kl) + rowbase;
        const float* crow = cs + (size_t)s * HD;
        const float* srow = sn + (size_t)s * HD;
        #pragma unroll
        for (int j = 0; j < 32; j++) {
            float lo = smf[r * 132 + dh + j];
            float hi = smf[r * 132 + dh + j + 64];
            float olo = lo * crow[dh + j]      - hi * srow[dh + j];
            float ohi = hi * crow[dh + j + 64] + lo * srow[dh + j + 64];
            __half a  = __float2half_rn(olo);
            __half bq = __float2half_rn(ohi);
            dsth[dh + j]      = a;
            dsth[dh + j + 64] = bq;
            dstl[dh + j]      = __float2half_rn(olo - __half2float(a));
            dstl[dh + j + 64] = __float2half_rn(ohi - __half2float(bq));
        }
    } else {
        __half* dst = g_vh + rowbase;
        #pragma unroll
        for (int j = 0; j < 32; j++) {
            dst[dh + j]      = __float2half_rn(smf[r * 132 + dh + j]);
            dst[dh + j + 64] = __float2half_rn(smf[r * 132 + dh + j + 64]);
        }
    }
}

// ---------------------------------------------------------------------------
// Output projection: out = ctx(fp16) @ Wo(fp16)^T, 1-term
// ---------------------------------------------------------------------------
__global__ __launch_bounds__(256, 2)
void outproj_mma_kernel(float* __restrict__ out)
{
    const int m0 = blockIdx.y * 128;
    const int n0 = blockIdx.x * 128;

    float acc[2][8][4];
    #pragma unroll
    for (int g = 0; g < 2; g++)
        #pragma unroll
        for (int j = 0; j < 8; j++)
            #pragma unroll
            for (int e = 0; e < 4; e++) acc[g][j][e] = 0.f;

    gemm_main1(g_cf, g_wof, m0, n0, acc);

    const int lane = threadIdx.x & 31;
    const int warp = threadIdx.x >> 5;
    const int wm = warp & 3, wn = warp >> 2;
    #pragma unroll
    for (int g = 0; g < 2; g++) {
        #pragma unroll
        for (int j = 0; j < 8; j++) {
            size_t row = (size_t)m0 + wm * 32 + g * 16 + (lane >> 2);
            int col = n0 + wn * 64 + (j >> 1) * 16 + (j & 1) * 8 + 2 * (lane & 3);
            *(float2*)&out[row * H_ + col] =
                make_float2(acc[g][j][0], acc[g][j][1]);
            *(float2*)&out[(row + 8) * H_ + col] =
                make_float2(acc[g][j][2], acc[g][j][3]);
        }
    }
}

// ---------------------------------------------------------------------------
// fp32 -> bf16 hi/lo split; fp32 -> fp16 convert
// ---------------------------------------------------------------------------
__global__ void split_kernel(const float* __restrict__ src,
                             __nv_bfloat16* __restrict__ hi,
                             __nv_bfloat16* __restrict__ lo, int n4)
{
    int i = blockIdx.x * blockDim.x + threadIdx.x;
    if (i >= n4) return;
    float4 v = ((const float4*)src)[i];
    __nv_bfloat16 h0 = __float2bfloat16(v.x), h1 = __float2bfloat16(v.y);
    __nv_bfloat16 h2 = __float2bfloat16(v.z), h3 = __float2bfloat16(v.w);
    __nv_bfloat16 l0 = __float2bfloat16(v.x - __bfloat162float(h0));
    __nv_bfloat16 l1 = __float2bfloat16(v.y - __bfloat162float(h1));
    __nv_bfloat16 l2 = __float2bfloat16(v.z - __bfloat162float(h2));
    __nv_bfloat16 l3 = __float2bfloat16(v.w - __bfloat162float(h3));
    ((__nv_bfloat162*)hi)[2*i]   = __nv_bfloat162(h0, h1);
    ((__nv_bfloat162*)hi)[2*i+1] = __nv_bfloat162(h2, h3);
    ((__nv_bfloat162*)lo)[2*i]   = __nv_bfloat162(l0, l1);
    ((__nv_bfloat162*)lo)[2*i+1] = __nv_bfloat162(l2, l3);
}

__global__ void cvt_kernel(const float* __restrict__ src,
                           __half* __restrict__ dst, int n4)
{
    int i = blockIdx.x * blockDim.x + threadIdx.x;
    if (i >= n4) return;
    float4 v = ((const float4*)src)[i];
    ((__half2*)dst)[2*i]   = __floats2half2_rn(v.x, v.y);
    ((__half2*)dst)[2*i+1] = __floats2half2_rn(v.z, v.w);
}

// ---------------------------------------------------------------------------
// Tensor-core causal flash attention (split-fp16 QK^T, single-fp16 PV).
// ---------------------------------------------------------------------------
__global__ __launch_bounds__(256, 1)
void attn_mma_kernel()
{
    extern __shared__ char smem[];
    __half* sQh = (__half*)smem;
    __half* sQl = sQh + ATILE;
    __half* sKh = sQl + ATILE;
    __half* sKl = sKh + ATILE;
    __half* sVh = sKl + ATILE;

    const int tid  = threadIdx.x;
    const int lane = tid & 31;
    const int warp = tid >> 5;
    const int lrow = lane & 7;
    const int lq   = lane >> 3;
    const int qt   = (gridDim.x - 1) - blockIdx.x;
    const int bh   = blockIdx.y;
    const int q0   = qt * 128;
    const size_t base = (size_t)bh * S_ * HD;

    const uint32_t sQh_u = smem_u32(sQh);
    const uint32_t sQl_u = smem_u32(sQl);
    const uint32_t sKh_u = smem_u32(sKh);
    const uint32_t sKl_u = smem_u32(sKl);
    const uint32_t sVh_u = smem_u32(sVh);

    #pragma unroll
    for (int it = 0; it < 8; it++) {
        int idx = it * 256 + tid;
        int r   = idx >> 4;
        int c8  = (idx & 15) * 8;
        size_t g = base + (size_t)(q0 + r) * HD + c8;
        uint32_t so = (uint32_t)(r * AST + c8) * 2;
        CPA16(sQh_u + so, (const char*)&g_qh[g]);
        CPA16(sQl_u + so, (const char*)&g_ql[g]);
    }
    CPA_COMMIT();
    CPA_WAIT0();
    __syncthreads();

    uint32_t qfh[8][4], qfl[8][4];
    {
        int row = warp * 16 + ((lq & 1) ? 8 : 0) + lrow;
        #pragma unroll
        for (int ks = 0; ks < 8; ks++) {
            int col = ks * 16 + ((lq & 2) ? 8 : 0);
            uint32_t so = (uint32_t)(row * AST + col) * 2;
            LDSM4(qfh[ks], sQh_u + so);
            LDSM4(qfl[ks], sQl_u + so);
        }
    }

    float o[16][4];
    #pragma unroll
    for (int j = 0; j < 16; j++)
        #pragma unroll
        for (int e = 0; e < 4; e++) o[j][e] = 0.f;
    float mr[2] = { -1e30f, -1e30f };
    float lr_[2] = { 0.f, 0.f };

    const int krow_b = ((lq & 2) ? 8 : 0) + lrow;
    const int kcol_b = ((lq & 1) ? 8 : 0);
    const int vrow_b = ((lq & 1) ? 8 : 0) + lrow;
    const int vcol_b = ((lq & 2) ? 8 : 0);
    const int myrow  = lane >> 2;
    const int mycol  = 2 * (lane & 3);

    for (int kt = 0; kt <= qt; kt++) {
        const int kb = kt * 128;
        __syncthreads();

        #pragma unroll
        for (int it = 0; it < 8; it++) {
            int idx = it * 256 + tid;
            int r   = idx >> 4;
            int c8  = (idx & 15) * 8;
            size_t g = base + (size_t)(kb + r) * HD + c8;
            uint32_t so = (uint32_t)(r * AST + c8) * 2;
            CPA16(sKh_u + so, (const char*)&g_kh[g]);
            CPA16(sKl_u + so, (const char*)&g_kl[g]);
            CPA16(sVh_u + so, (const char*)&g_vh[g]);
        }
        CPA_COMMIT();
        CPA_WAIT0();
        __syncthreads();

        // ---- S = Qh Kh^T + Qh Kl^T + Ql Kh^T ----
        float sf[16][4];
        #pragma unroll
        for (int j = 0; j < 16; j++)
            #pragma unroll
            for (int e = 0; e < 4; e++) sf[j][e] = 0.f;

        #pragma unroll
        for (int ks = 0; ks < 8; ks++) {
            #pragma unroll
            for (int jj = 0; jj < 8; jj += 2) {
                int col = ks * 16 + kcol_b;
                uint32_t so0 = (uint32_t)(((jj    ) * 16 + krow_b) * AST + col) * 2;
                uint32_t so1 = (uint32_t)(((jj + 1) * 16 + krow_b) * AST + col) * 2;
                uint32_t kfh0[4], kfl0[4], kfh1[4], kfl1[4];
                LDSM4(kfh0, sKh_u + so0);
                LDSM4(kfh1, sKh_u + so1);
                LDSM4(kfl0, sKl_u + so0);
                LDSM4(kfl1, sKl_u + so1);
                MMAH(sf[2*jj],   qfh[ks], kfh0[0], kfh0[1]);
                MMAH(sf[2*jj+1], qfh[ks], kfh0[2], kfh0[3]);
                MMAH(sf[2*jj+2], qfh[ks], kfh1[0], kfh1[1]);
                MMAH(sf[2*jj+3], qfh[ks], kfh1[2], kfh1[3]);

                MMAH(sf[2*jj],   qfh[ks], kfl0[0], kfl0[1]);
                MMAH(sf[2*jj+1], qfh[ks], kfl0[2], kfl0[3]);
                MMAH(sf[2*jj+2], qfh[ks], kfl1[0], kfl1[1]);
                MMAH(sf[2*jj+3], qfh[ks], kfl1[2], kfl1[3]);

                MMAH(sf[2*jj],   qfl[ks], kfh0[0], kfh0[1]);
                MMAH(sf[2*jj+1], qfl[ks], kfh0[2], kfh0[3]);
                MMAH(sf[2*jj+2], qfl[ks], kfh1[0], kfh1[1]);
                MMAH(sf[2*jj+3], qfl[ks], kfh1[2], kfh1[3]);
            }
        }

        // ---- online softmax ----
        const bool diag = (kt == qt);
        const int grow0 = q0 + warp * 16 + myrow;
        #pragma unroll
        for (int rr = 0; rr < 2; rr++) {
            const int grow = grow0 + rr * 8;
            float mx = -1e30f;
            #pragma unroll
            for (int j = 0; j < 16; j++) {
                #pragma unroll
                for (int e = 0; e < 2; e++) {
                    float v = sf[j][rr * 2 + e] * SCALE;
                    if (diag && (kb + j * 8 + mycol + e) > grow) v = -1e30f;
                    sf[j][rr * 2 + e] = v;
                    mx = fmaxf(mx, v);
                }
            }
            mx = fmaxf(mx, __shfl_xor_sync(0xffffffffu, mx, 1));
            mx = fmaxf(mx, __shfl_xor_sync(0xffffffffu, mx, 2));
            float mnew  = fmaxf(mr[rr], mx);
            float alpha = __expf(mr[rr] - mnew);
            mr[rr] = mnew;
            float ls = 0.f;
            #pragma unroll
            for (int j = 0; j < 16; j++) {
                #pragma unroll
                for (int e = 0; e < 2; e++) {
                    float p = __expf(sf[j][rr * 2 + e] - mnew);
                    sf[j][rr * 2 + e] = p;
                    ls += p;
                }
            }
            ls += __shfl_xor_sync(0xffffffffu, ls, 1);
            ls += __shfl_xor_sync(0xffffffffu, ls, 2);
            lr_[rr] = lr_[rr] * alpha + ls;
            #pragma unroll
            for (int j = 0; j < 16; j++) {
                o[j][rr * 2]     *= alpha;
                o[j][rr * 2 + 1] *= alpha;
            }
        }

        // ---- pack P to fp16 A-frags ----
        uint32_t pf[8][4];
        #pragma unroll
        for (int j = 0; j < 8; j++) {
            __half2 h;
            h = __floats2half2_rn(sf[2*j][0],   sf[2*j][1]);   pf[j][0] = *(uint32_t*)&h;
            h = __floats2half2_rn(sf[2*j][2],   sf[2*j][3]);   pf[j][1] = *(uint32_t*)&h;
            h = __floats2half2_rn(sf[2*j+1][0], sf[2*j+1][1]); pf[j][2] = *(uint32_t*)&h;
            h = __floats2half2_rn(sf[2*j+1][2], sf[2*j+1][3]); pf[j][3] = *(uint32_t*)&h;
        }

        // ---- O += P · Vh (single product) ----
        #pragma unroll
        for (int j = 0; j < 8; j++) {
            int row = j * 16 + vrow_b;
            #pragma unroll
            for (int dd = 0; dd < 8; dd += 2) {
                uint32_t so0 = (uint32_t)(row * AST + (dd    ) * 16 + vcol_b) * 2;
                uint32_t so1 = (uint32_t)(row * AST + (dd + 1) * 16 + vcol_b) * 2;
                uint32_t vh0[4], vh1[4];
                LDSM4T(vh0, sVh_u + so0);
                LDSM4T(vh1, sVh_u + so1);
                MMAH(o[2*dd],   pf[j], vh0[0], vh0[1]);
                MMAH(o[2*dd+1], pf[j], vh0[2], vh0[3]);
                MMAH(o[2*dd+2], pf[j], vh1[0], vh1[1]);
                MMAH(o[2*dd+3], pf[j], vh1[2], vh1[3]);
            }
        }
    }

    // ---- epilogue: normalize, write ctx fp16 ----
    const int b = bh >> 4;
    const int h = bh & 15;
    float inv0 = 1.0f / lr_[0];
    float inv1 = 1.0f / lr_[1];
    const int srow = q0 + warp * 16 + myrow;
    #pragma unroll
    for (int j = 0; j < 16; j++) {
        int col = j * 8 + mycol;
        #pragma unroll
        for (int rr = 0; rr < 2; rr++) {
            float v0 = o[j][rr * 2]     * (rr ? inv1 : inv0);
            float v1 = o[j][rr * 2 + 1] * (rr ? inv1 : inv0);
            size_t off = ((size_t)(b * S_) + srow + rr * 8) * H_ + h * HD + col;
            *(__half2*)&g_cf[off] = __floats2half2_rn(v0, v1);
        }
    }
}

// ---------------------------------------------------------------------------
extern "C" void kernel_launch(void* const* d_in, const int* in_sizes, int n_in,
                              void* d_out, int out_size)
{
    (void)in_sizes; (void)n_in; (void)out_size;
    const float* x  = (const float*)d_in[0];
    const float* Wq = (const float*)d_in[1];
    const float* Wk = (const float*)d_in[2];
    const float* Wv = (const float*)d_in[3];
    const float* Wo = (const float*)d_in[4];
    const float* cs = (const float*)d_in[5];
    const float* sn = (const float*)d_in[6];
    float* out = (float*)d_out;

    void *pxh, *pxl, *pwh, *pwl, *pxf, *pwvf, *pwof;
    cudaGetSymbolAddress(&pxh, g_xh);
    cudaGetSymbolAddress(&pxl, g_xl);
    cudaGetSymbolAddress(&pwh, g_wh);
    cudaGetSymbolAddress(&pwl, g_wl);
    cudaGetSymbolAddress(&pxf, g_xf);
    cudaGetSymbolAddress(&pwvf, g_wvf);
    cudaGetSymbolAddress(&pwof, g_wof);

    {
        int n4 = MTOT * H_ / 4;
        int w4 = H_ * H_ / 4;
        split_kernel<<<(n4 + 255) / 256, 256>>>(x, (__nv_bfloat16*)pxh,
                                                (__nv_bfloat16*)pxl, n4);
        split_kernel<<<(w4 + 255) / 256, 256>>>(Wq, (__nv_bfloat16*)pwh,
                                                (__nv_bfloat16*)pwl, w4);
        split_kernel<<<(w4 + 255) / 256, 256>>>(Wk, (__nv_bfloat16*)pwh + HH,
                                                (__nv_bfloat16*)pwl + HH, w4);
        cvt_kernel<<<(n4 + 255) / 256, 256>>>(x,  (__half*)pxf,  n4);
        cvt_kernel<<<(w4 + 255) / 256, 256>>>(Wv, (__half*)pwvf, w4);
        cvt_kernel<<<(w4 + 255) / 256, 256>>>(Wo, (__half*)pwof, w4);
    }

    cudaFuncSetAttribute(qkv_mma_kernel,
                         cudaFuncAttributeMaxDynamicSharedMemorySize, GEMM_SMEM);
    qkv_mma_kernel<<<dim3(H_ / 128, MTOT / 128, 3), 256, GEMM_SMEM>>>(cs, sn);

    cudaFuncSetAttribute(attn_mma_kernel,
                         cudaFuncAttributeMaxDynamicSharedMemorySize, ATTN_SMEM);
    attn_mma_kernel<<<dim3(S_ / 128, B_ * NH), 256, ATTN_SMEM>>>();

    cudaFuncSetAttribute(outproj_mma_kernel,
                         cudaFuncAttributeMaxDynamicSharedMemorySize, OUT_SMEM);
    outproj_mma_kernel<<<dim3(H_ / 128, MTOT / 128), 256, OUT_SMEM>>>(out);
}